// round 1
// baseline (speedup 1.0000x reference)
#include <cuda_runtime.h>
#include <cuda_bf16.h>
#include <cstdint>

#define BSZ 2
#define SEQLEN 2048
#define NHEADS 32
#define HDIM 128
#define DIM 4096
#define NTOK (BSZ * SEQLEN)              // 4096
#define OUT_ELEMS ((size_t)NTOK * DIM)   // 16,777,216
#define KV_ELEMS OUT_ELEMS               // per k or v plane

// Scratch (device globals; no allocation allowed)
__device__ float g_Q[OUT_ELEMS];
__device__ float g_attn[OUT_ELEMS];

// ---------------------------------------------------------------------------
// GEMM: C[m][n] = sum_k A[m*K+k] * B[n*K+k]   (A row-major, B row-major, C = A @ B^T)
// 128x128 tile, K-step 8, 256 threads, 8x8 per-thread micro-tile.
// ---------------------------------------------------------------------------
__global__ __launch_bounds__(256) void gemm_tn(const float* __restrict__ A,
                                               const float* __restrict__ B,
                                               float* __restrict__ C,
                                               int M, int N, int K) {
    __shared__ float As[8][128];
    __shared__ float Bs[8][128];

    const int bm = blockIdx.y * 128;
    const int bn = blockIdx.x * 128;
    const int tid = threadIdx.x;
    const int tm = (tid >> 4) << 3;   // 0..120
    const int tn = (tid & 15) << 3;   // 0..120
    const int lr = tid >> 1;          // 0..127
    const int lc = (tid & 1) << 2;    // 0 or 4

    const float* Ap = A + (size_t)(bm + lr) * K + lc;
    const float* Bp = B + (size_t)(bn + lr) * K + lc;

    float acc[8][8];
#pragma unroll
    for (int i = 0; i < 8; i++)
#pragma unroll
        for (int j = 0; j < 8; j++) acc[i][j] = 0.f;

    for (int k0 = 0; k0 < K; k0 += 8) {
        float4 a = *(const float4*)(Ap + k0);
        float4 b = *(const float4*)(Bp + k0);
        As[lc + 0][lr] = a.x; As[lc + 1][lr] = a.y;
        As[lc + 2][lr] = a.z; As[lc + 3][lr] = a.w;
        Bs[lc + 0][lr] = b.x; Bs[lc + 1][lr] = b.y;
        Bs[lc + 2][lr] = b.z; Bs[lc + 3][lr] = b.w;
        __syncthreads();
#pragma unroll
        for (int kk = 0; kk < 8; kk++) {
            float4 a0 = *(const float4*)&As[kk][tm];
            float4 a1 = *(const float4*)&As[kk][tm + 4];
            float4 b0 = *(const float4*)&Bs[kk][tn];
            float4 b1 = *(const float4*)&Bs[kk][tn + 4];
            float ar[8] = {a0.x, a0.y, a0.z, a0.w, a1.x, a1.y, a1.z, a1.w};
            float br[8] = {b0.x, b0.y, b0.z, b0.w, b1.x, b1.y, b1.z, b1.w};
#pragma unroll
            for (int i = 0; i < 8; i++)
#pragma unroll
                for (int j = 0; j < 8; j++) acc[i][j] = fmaf(ar[i], br[j], acc[i][j]);
        }
        __syncthreads();
    }

#pragma unroll
    for (int i = 0; i < 8; i++) {
        float* Cp = C + (size_t)(bm + tm + i) * N + bn + tn;
        float4 c0 = {acc[i][0], acc[i][1], acc[i][2], acc[i][3]};
        float4 c1 = {acc[i][4], acc[i][5], acc[i][6], acc[i][7]};
        *(float4*)(Cp) = c0;
        *(float4*)(Cp + 4) = c1;
    }
}

// ---------------------------------------------------------------------------
// Rotary: apply RoPE in-place to Q (scratch) and K (in output hidden region).
// One thread per (b, s, h, pair).
// ---------------------------------------------------------------------------
__global__ __launch_bounds__(256) void rotary_kernel(float* __restrict__ Q,
                                                     float* __restrict__ Kh,
                                                     const float* __restrict__ fc) {
    int idx = blockIdx.x * blockDim.x + threadIdx.x;
    const int total = BSZ * SEQLEN * NHEADS * (HDIM / 2);
    if (idx >= total) return;
    int p = idx & 63;
    int h = (idx >> 6) & 31;
    int s = (idx >> 11) & (SEQLEN - 1);
    int b = idx >> (11 + 11);  // 6 + 5 + 11 bits

    float c = fc[(s * 64 + p) * 2];
    float sn = fc[(s * 64 + p) * 2 + 1];

    size_t base = (((size_t)(b * SEQLEN + s) * NHEADS) + h) * HDIM + p * 2;

    float2 q = *(float2*)(Q + base);
    float2 k = *(float2*)(Kh + base);
    float2 qo = {q.x * c - q.y * sn, q.x * sn + q.y * c};
    float2 ko = {k.x * c - k.y * sn, k.x * sn + k.y * c};
    *(float2*)(Q + base) = qo;
    *(float2*)(Kh + base) = ko;
}

// ---------------------------------------------------------------------------
// Fused causal attention (flash style): one block per (q-tile 64, head, batch).
// Online softmax over 64-wide key tiles. Layouts: [B,S,H,D].
// ---------------------------------------------------------------------------
#define QS_STRIDE 129
#define VS_STRIDE 132
#define SS_STRIDE 65

__global__ __launch_bounds__(256) void attn_kernel(const float* __restrict__ Q,
                                                   const float* __restrict__ Kh,
                                                   const float* __restrict__ Vh,
                                                   float* __restrict__ O) {
    extern __shared__ float sm[];
    float* Qs = sm;                       // 64 * 129
    float* Ks = Qs + 64 * QS_STRIDE;      // 64 * 129
    float* Vs = Ks + 64 * QS_STRIDE;      // 64 * 132
    float* Ss = Vs + 64 * VS_STRIDE;      // 64 * 65
    float* mrow = Ss + 64 * SS_STRIDE;    // 64
    float* lrow = mrow + 64;              // 64
    float* arow = lrow + 64;              // 64

    const int qb = blockIdx.x;
    const int h = blockIdx.y;
    const int b = blockIdx.z;
    const int tid = threadIdx.x;
    const float scale = 0.08838834764831845f;  // 1/sqrt(128)

    // load Q tile [64 x 128]
    size_t qbase = (((size_t)(b * SEQLEN + qb * 64) * NHEADS) + h) * HDIM;
    for (int e = tid; e < 64 * 32; e += 256) {
        int r = e >> 5, c4 = (e & 31) << 2;
        float4 v = *(const float4*)(Q + qbase + (size_t)r * (NHEADS * HDIM) + c4);
        Qs[r * QS_STRIDE + c4] = v.x;
        Qs[r * QS_STRIDE + c4 + 1] = v.y;
        Qs[r * QS_STRIDE + c4 + 2] = v.z;
        Qs[r * QS_STRIDE + c4 + 3] = v.w;
    }
    if (tid < 64) { mrow[tid] = -1e30f; lrow[tid] = 0.f; }

    const int ig = tid >> 4;   // 0..15: row group (rows ig*4 .. ig*4+3)
    const int cg = tid & 15;   // 0..15: col group (S cols cg*4.. ; PV cols cg*8..)

    float Oacc[4][8];
#pragma unroll
    for (int i = 0; i < 4; i++)
#pragma unroll
        for (int c = 0; c < 8; c++) Oacc[i][c] = 0.f;

    for (int kb = 0; kb <= qb; kb++) {
        __syncthreads();
        // load K, V tiles [64 x 128]
        size_t kbase = (((size_t)(b * SEQLEN + kb * 64) * NHEADS) + h) * HDIM;
        for (int e = tid; e < 64 * 32; e += 256) {
            int r = e >> 5, c4 = (e & 31) << 2;
            float4 kv = *(const float4*)(Kh + kbase + (size_t)r * (NHEADS * HDIM) + c4);
            Ks[r * QS_STRIDE + c4] = kv.x;
            Ks[r * QS_STRIDE + c4 + 1] = kv.y;
            Ks[r * QS_STRIDE + c4 + 2] = kv.z;
            Ks[r * QS_STRIDE + c4 + 3] = kv.w;
            float4 vv = *(const float4*)(Vh + kbase + (size_t)r * (NHEADS * HDIM) + c4);
            *(float4*)&Vs[r * VS_STRIDE + c4] = vv;
        }
        __syncthreads();

        // S = Q @ K^T  (4x4 per thread)
        float sacc[4][4];
#pragma unroll
        for (int i = 0; i < 4; i++)
#pragma unroll
            for (int j = 0; j < 4; j++) sacc[i][j] = 0.f;
        for (int d = 0; d < 128; d++) {
            float qr[4], kr[4];
#pragma unroll
            for (int ii = 0; ii < 4; ii++) qr[ii] = Qs[(ig * 4 + ii) * QS_STRIDE + d];
#pragma unroll
            for (int jj = 0; jj < 4; jj++) kr[jj] = Ks[(cg * 4 + jj) * QS_STRIDE + d];
#pragma unroll
            for (int ii = 0; ii < 4; ii++)
#pragma unroll
                for (int jj = 0; jj < 4; jj++)
                    sacc[ii][jj] = fmaf(qr[ii], kr[jj], sacc[ii][jj]);
        }
        const int gq0 = qb * 64, gk0 = kb * 64;
#pragma unroll
        for (int ii = 0; ii < 4; ii++)
#pragma unroll
            for (int jj = 0; jj < 4; jj++) {
                float s = sacc[ii][jj] * scale;
                if (gk0 + cg * 4 + jj > gq0 + ig * 4 + ii) s += -1e9f;
                Ss[(ig * 4 + ii) * SS_STRIDE + cg * 4 + jj] = s;
            }
        __syncthreads();

        // online softmax row update
        if (tid < 64) {
            float m_old = mrow[tid];
            float m = m_old;
            for (int j = 0; j < 64; j++) m = fmaxf(m, Ss[tid * SS_STRIDE + j]);
            float sum = 0.f;
            for (int j = 0; j < 64; j++) {
                float p = __expf(Ss[tid * SS_STRIDE + j] - m);
                Ss[tid * SS_STRIDE + j] = p;
                sum += p;
            }
            float alpha = __expf(m_old - m);
            lrow[tid] = lrow[tid] * alpha + sum;
            mrow[tid] = m;
            arow[tid] = alpha;
        }
        __syncthreads();

        // rescale + P @ V  (rows ig*4.., cols cg*8..)
#pragma unroll
        for (int ii = 0; ii < 4; ii++) {
            float a = arow[ig * 4 + ii];
#pragma unroll
            for (int c = 0; c < 8; c++) Oacc[ii][c] *= a;
        }
        for (int j = 0; j < 64; j++) {
            float4 v0 = *(const float4*)&Vs[j * VS_STRIDE + cg * 8];
            float4 v1 = *(const float4*)&Vs[j * VS_STRIDE + cg * 8 + 4];
            float vr[8] = {v0.x, v0.y, v0.z, v0.w, v1.x, v1.y, v1.z, v1.w};
            float p[4];
#pragma unroll
            for (int ii = 0; ii < 4; ii++) p[ii] = Ss[(ig * 4 + ii) * SS_STRIDE + j];
#pragma unroll
            for (int ii = 0; ii < 4; ii++)
#pragma unroll
                for (int c = 0; c < 8; c++) Oacc[ii][c] = fmaf(p[ii], vr[c], Oacc[ii][c]);
        }
    }

    // write O (normalized)
    size_t obase = (((size_t)(b * SEQLEN + qb * 64) * NHEADS) + h) * HDIM;
#pragma unroll
    for (int ii = 0; ii < 4; ii++) {
        int i = ig * 4 + ii;
        float inv = 1.f / lrow[i];
        float4 o0 = {Oacc[ii][0] * inv, Oacc[ii][1] * inv, Oacc[ii][2] * inv, Oacc[ii][3] * inv};
        float4 o1 = {Oacc[ii][4] * inv, Oacc[ii][5] * inv, Oacc[ii][6] * inv, Oacc[ii][7] * inv};
        float* Op = O + obase + (size_t)i * (NHEADS * HDIM) + cg * 8;
        *(float4*)(Op) = o0;
        *(float4*)(Op + 4) = o1;
    }
}

// ---------------------------------------------------------------------------
extern "C" void kernel_launch(void* const* d_in, const int* in_sizes, int n_in,
                              void* d_out, int out_size) {
    const float* x  = (const float*)d_in[0];
    const float* fc = (const float*)d_in[1];
    // d_in[2] = mask (replicated analytically), d_in[3] = hidden_state (fully overwritten)
    const float* wq = (const float*)d_in[4];
    const float* wk = (const float*)d_in[5];
    const float* wv = (const float*)d_in[6];
    const float* wo = (const float*)d_in[7];

    float* out = (float*)d_out;                 // [B,S,DIM]
    float* Kh = out + OUT_ELEMS;                // new_hidden[0]: [B,S,H,D]
    float* Vh = Kh + KV_ELEMS;                  // new_hidden[1]

    float* qbuf = nullptr;
    float* abuf = nullptr;
    cudaGetSymbolAddress((void**)&qbuf, g_Q);
    cudaGetSymbolAddress((void**)&abuf, g_attn);

    dim3 ggrid(DIM / 128, NTOK / 128);
    gemm_tn<<<ggrid, 256>>>(x, wq, qbuf, NTOK, DIM, DIM);
    gemm_tn<<<ggrid, 256>>>(x, wk, Kh, NTOK, DIM, DIM);
    gemm_tn<<<ggrid, 256>>>(x, wv, Vh, NTOK, DIM, DIM);

    int rtotal = BSZ * SEQLEN * NHEADS * (HDIM / 2);
    rotary_kernel<<<(rtotal + 255) / 256, 256>>>(qbuf, Kh, fc);

    int smem = (64 * QS_STRIDE * 2 + 64 * VS_STRIDE + 64 * SS_STRIDE + 192) * sizeof(float);
    cudaFuncSetAttribute(attn_kernel, cudaFuncAttributeMaxDynamicSharedMemorySize, smem);
    attn_kernel<<<dim3(SEQLEN / 64, NHEADS, BSZ), 256, smem>>>(qbuf, Kh, Vh, abuf);

    gemm_tn<<<ggrid, 256>>>(abuf, wo, out, NTOK, DIM, DIM);
}

// round 3
// speedup vs baseline: 2.0653x; 2.0653x over previous
#include <cuda_runtime.h>
#include <cuda_bf16.h>
#include <cstdint>

#define BSZ 2
#define SEQLEN 2048
#define NHEADS 32
#define HDIM 128
#define DIM 4096
#define NTOK (BSZ * SEQLEN)              // 4096
#define OUT_ELEMS ((size_t)NTOK * DIM)   // 16,777,216

// ---------------- GEMM tiling ----------------
#define BK 32
#define CHUNKS (DIM / BK)                // 128
#define SSTRIDE 40                       // smem row stride in bf16 elems (80B)
#define MAT_B (128 * SSTRIDE * 2)        // 10240 B per matrix per stage
#define STAGE_B (4 * MAT_B)              // Ah, Al, Bh, Bl = 40960 B
#define NSTAGE 3
#define GEMM_SMEM (NSTAGE * STAGE_B)     // 122880 B

// ---------------- scratch (device globals; no allocation allowed) -----------
__device__ __align__(256) float g_Q[OUT_ELEMS];
__device__ __align__(256) float g_attn[OUT_ELEMS];
__device__ __align__(256) __nv_bfloat16 g_xh[OUT_ELEMS];
__device__ __align__(256) __nv_bfloat16 g_xl[OUT_ELEMS];
__device__ __align__(256) __nv_bfloat16 g_wh[4ull * DIM * DIM];
__device__ __align__(256) __nv_bfloat16 g_wl[4ull * DIM * DIM];
__device__ __align__(256) __nv_bfloat16 g_ah[OUT_ELEMS];
__device__ __align__(256) __nv_bfloat16 g_al[OUT_ELEMS];

// ---------------- PTX helpers ------------------------------------------------
__device__ __forceinline__ uint32_t smem_u32(const void* p) {
    uint32_t a;
    asm("{ .reg .u64 t; cvta.to.shared.u64 t, %1; cvt.u32.u64 %0, t; }" : "=r"(a) : "l"(p));
    return a;
}
__device__ __forceinline__ void cp16(uint32_t dst, const void* src) {
    asm volatile("cp.async.cg.shared.global [%0], [%1], 16;" :: "r"(dst), "l"(src));
}
__device__ __forceinline__ void ldsm4(uint32_t* r, uint32_t addr) {
    asm volatile("ldmatrix.sync.aligned.m8n8.x4.shared.b16 {%0,%1,%2,%3}, [%4];"
        : "=r"(r[0]), "=r"(r[1]), "=r"(r[2]), "=r"(r[3]) : "r"(addr));
}
__device__ __forceinline__ void mma16816(float* c, const uint32_t* a, const uint32_t* b) {
    asm volatile("mma.sync.aligned.m16n8k16.row.col.f32.bf16.bf16.f32 "
        "{%0,%1,%2,%3}, {%4,%5,%6,%7}, {%8,%9}, {%0,%1,%2,%3};"
        : "+f"(c[0]), "+f"(c[1]), "+f"(c[2]), "+f"(c[3])
        : "r"(a[0]), "r"(a[1]), "r"(a[2]), "r"(a[3]), "r"(b[0]), "r"(b[1]));
}

// ---------------------------------------------------------------------------
// fp32 -> (bf16 hi, bf16 lo), plain row-major.
// ---------------------------------------------------------------------------
__global__ __launch_bounds__(256) void convert_split(const float* __restrict__ src,
                                                     __nv_bfloat16* __restrict__ hi,
                                                     __nv_bfloat16* __restrict__ lo) {
    size_t i = (size_t)blockIdx.x * blockDim.x + threadIdx.x;  // one per 4 elems
    float4 v = ((const float4*)src)[i];
    float f[4] = {v.x, v.y, v.z, v.w};
    __nv_bfloat16 h4[4], l4[4];
#pragma unroll
    for (int j = 0; j < 4; j++) {
        h4[j] = __float2bfloat16(f[j]);
        l4[j] = __float2bfloat16(f[j] - __bfloat162float(h4[j]));
    }
    ((uint2*)hi)[i] = *(uint2*)h4;
    ((uint2*)lo)[i] = *(uint2*)l4;
}

// ---------------------------------------------------------------------------
// Split-bf16 mma.sync GEMM: C[m][n] = sum_k A[m][k]*B[n][k]  (both row-major)
// 128x128 CTA tile, BK=32, 3-stage cp.async, 8 warps of 64x32.
// ---------------------------------------------------------------------------
__global__ __launch_bounds__(256)
void gemm_mma(const __nv_bfloat16* __restrict__ Ah, const __nv_bfloat16* __restrict__ Al,
              const __nv_bfloat16* __restrict__ Bh, const __nv_bfloat16* __restrict__ Bl,
              float* __restrict__ C) {
    extern __shared__ char sm_raw[];
    const uint32_t base = smem_u32(sm_raw);
    const int tid = threadIdx.x;
    const int warp = tid >> 5, lane = tid & 31;
    const int wm = warp & 1, wn = warp >> 1;     // 2 x 4 warp grid
    const int nt = blockIdx.x, mt = blockIdx.y;

    const __nv_bfloat16* gsrc0 = Ah + (size_t)mt * 128 * DIM;
    const __nv_bfloat16* gsrc1 = Al + (size_t)mt * 128 * DIM;
    const __nv_bfloat16* gsrc2 = Bh + (size_t)nt * 128 * DIM;
    const __nv_bfloat16* gsrc3 = Bl + (size_t)nt * 128 * DIM;

#define LOAD_CHUNK(c, s)                                                         \
    do {                                                                         \
        const int ch_ = tid & 3;                                                 \
        _Pragma("unroll")                                                        \
        for (int i_ = 0; i_ < 8; i_++) {                                         \
            const int mat_ = i_ >> 1;                                            \
            const int r_ = (((i_ & 1) << 6) + (tid >> 2)) & 127;                 \
            uint32_t dst_ = base + (s) * STAGE_B + mat_ * MAT_B +                \
                            r_ * (SSTRIDE * 2) + ch_ * 16;                       \
            const __nv_bfloat16* sp_ =                                           \
                (mat_ == 0 ? gsrc0 : mat_ == 1 ? gsrc1 : mat_ == 2 ? gsrc2       \
                                                       : gsrc3);                 \
            cp16(dst_, sp_ + (size_t)r_ * DIM + (c) * BK + ch_ * 8);             \
        }                                                                        \
        asm volatile("cp.async.commit_group;" ::: "memory");                     \
    } while (0)

    LOAD_CHUNK(0, 0);
    LOAD_CHUNK(1, 1);

    // invariant smem offsets (bytes within a matrix)
    const uint32_t aOff = (wm * 64 + (lane & 15)) * (SSTRIDE * 2) + ((lane >> 4) << 3) * 2;
    const uint32_t bOff = (wn * 32 + (lane & 7) + ((lane & 16) >> 1)) * (SSTRIDE * 2) + (lane & 8) * 2;

    float c[4][4][4];
#pragma unroll
    for (int mi = 0; mi < 4; mi++)
#pragma unroll
        for (int ni = 0; ni < 4; ni++)
#pragma unroll
            for (int j = 0; j < 4; j++) c[mi][ni][j] = 0.f;

    for (int ck = 0; ck < CHUNKS; ck++) {
        const int s = ck % 3;
        if (ck + 2 < CHUNKS) asm volatile("cp.async.wait_group 1;" ::: "memory");
        else                 asm volatile("cp.async.wait_group 0;" ::: "memory");
        __syncthreads();

        if (ck + 2 < CHUNKS) LOAD_CHUNK(ck + 2, (ck + 2) % 3);

        const uint32_t sb = base + s * STAGE_B;
        const uint32_t aHi = sb + aOff;
        const uint32_t aLo = sb + MAT_B + aOff;
        const uint32_t bHi = sb + 2 * MAT_B + bOff;
        const uint32_t bLo = sb + 3 * MAT_B + bOff;

#pragma unroll
        for (int kk = 0; kk < 2; kk++) {
            const uint32_t kb = kk * 32;   // 16 elems * 2B
            uint32_t bh[8], bl[8];
            ldsm4(bh + 0, bHi + kb);
            ldsm4(bh + 4, bHi + kb + 16 * SSTRIDE * 2);
            ldsm4(bl + 0, bLo + kb);
            ldsm4(bl + 4, bLo + kb + 16 * SSTRIDE * 2);
#pragma unroll
            for (int mi = 0; mi < 4; mi++) {
                uint32_t ah[4], al[4];
                ldsm4(ah, aHi + kb + mi * 16 * SSTRIDE * 2);
                ldsm4(al, aLo + kb + mi * 16 * SSTRIDE * 2);
#pragma unroll
                for (int ni = 0; ni < 4; ni++) {
                    mma16816(c[mi][ni], ah, &bh[ni * 2]);
                    mma16816(c[mi][ni], al, &bh[ni * 2]);
                    mma16816(c[mi][ni], ah, &bl[ni * 2]);
                }
            }
        }
    }

    // epilogue
    float* Cw = C + (size_t)(mt * 128 + wm * 64) * DIM + nt * 128 + wn * 32;
    const int cr = lane >> 2, cc = (lane & 3) * 2;
#pragma unroll
    for (int mi = 0; mi < 4; mi++)
#pragma unroll
        for (int ni = 0; ni < 4; ni++) {
            float* p0 = Cw + (size_t)(mi * 16 + cr) * DIM + ni * 8 + cc;
            float* p1 = p0 + 8 * DIM;
            *(float2*)p0 = make_float2(c[mi][ni][0], c[mi][ni][1]);
            *(float2*)p1 = make_float2(c[mi][ni][2], c[mi][ni][3]);
        }
}

// ---------------------------------------------------------------------------
// Rotary (unchanged)
// ---------------------------------------------------------------------------
__global__ __launch_bounds__(256) void rotary_kernel(float* __restrict__ Q,
                                                     float* __restrict__ Kh,
                                                     const float* __restrict__ fc) {
    int idx = blockIdx.x * blockDim.x + threadIdx.x;
    const int total = BSZ * SEQLEN * NHEADS * (HDIM / 2);
    if (idx >= total) return;
    int p = idx & 63;
    int h = (idx >> 6) & 31;
    int s = (idx >> 11) & (SEQLEN - 1);
    int b = idx >> 22;

    float c = fc[(s * 64 + p) * 2];
    float sn = fc[(s * 64 + p) * 2 + 1];

    size_t basei = (((size_t)(b * SEQLEN + s) * NHEADS) + h) * HDIM + p * 2;

    float2 q = *(float2*)(Q + basei);
    float2 k = *(float2*)(Kh + basei);
    float2 qo = {q.x * c - q.y * sn, q.x * sn + q.y * c};
    float2 ko = {k.x * c - k.y * sn, k.x * sn + k.y * c};
    *(float2*)(Q + basei) = qo;
    *(float2*)(Kh + basei) = ko;
}

// ---------------------------------------------------------------------------
// Fused causal attention (fp32, unchanged from round 1)
// ---------------------------------------------------------------------------
#define QS_STRIDE 129
#define VS_STRIDE 132
#define SS_STRIDE 65

__global__ __launch_bounds__(256) void attn_kernel(const float* __restrict__ Q,
                                                   const float* __restrict__ Kh,
                                                   const float* __restrict__ Vh,
                                                   float* __restrict__ O) {
    extern __shared__ float smf[];
    float* Qs = smf;
    float* Ks = Qs + 64 * QS_STRIDE;
    float* Vs = Ks + 64 * QS_STRIDE;
    float* Ss = Vs + 64 * VS_STRIDE;
    float* mrow = Ss + 64 * SS_STRIDE;
    float* lrow = mrow + 64;
    float* arow = lrow + 64;

    const int qb = blockIdx.x;
    const int h = blockIdx.y;
    const int b = blockIdx.z;
    const int tid = threadIdx.x;
    const float scale = 0.08838834764831845f;

    size_t qbase = (((size_t)(b * SEQLEN + qb * 64) * NHEADS) + h) * HDIM;
    for (int e = tid; e < 64 * 32; e += 256) {
        int r = e >> 5, c4 = (e & 31) << 2;
        float4 v = *(const float4*)(Q + qbase + (size_t)r * (NHEADS * HDIM) + c4);
        Qs[r * QS_STRIDE + c4] = v.x;
        Qs[r * QS_STRIDE + c4 + 1] = v.y;
        Qs[r * QS_STRIDE + c4 + 2] = v.z;
        Qs[r * QS_STRIDE + c4 + 3] = v.w;
    }
    if (tid < 64) { mrow[tid] = -1e30f; lrow[tid] = 0.f; }

    const int ig = tid >> 4;
    const int cg = tid & 15;

    float Oacc[4][8];
#pragma unroll
    for (int i = 0; i < 4; i++)
#pragma unroll
        for (int c = 0; c < 8; c++) Oacc[i][c] = 0.f;

    for (int kb = 0; kb <= qb; kb++) {
        __syncthreads();
        size_t kbase = (((size_t)(b * SEQLEN + kb * 64) * NHEADS) + h) * HDIM;
        for (int e = tid; e < 64 * 32; e += 256) {
            int r = e >> 5, c4 = (e & 31) << 2;
            float4 kv = *(const float4*)(Kh + kbase + (size_t)r * (NHEADS * HDIM) + c4);
            Ks[r * QS_STRIDE + c4] = kv.x;
            Ks[r * QS_STRIDE + c4 + 1] = kv.y;
            Ks[r * QS_STRIDE + c4 + 2] = kv.z;
            Ks[r * QS_STRIDE + c4 + 3] = kv.w;
            float4 vv = *(const float4*)(Vh + kbase + (size_t)r * (NHEADS * HDIM) + c4);
            *(float4*)&Vs[r * VS_STRIDE + c4] = vv;
        }
        __syncthreads();

        float sacc[4][4];
#pragma unroll
        for (int i = 0; i < 4; i++)
#pragma unroll
            for (int j = 0; j < 4; j++) sacc[i][j] = 0.f;
        for (int d = 0; d < 128; d++) {
            float qr[4], kr[4];
#pragma unroll
            for (int ii = 0; ii < 4; ii++) qr[ii] = Qs[(ig * 4 + ii) * QS_STRIDE + d];
#pragma unroll
            for (int jj = 0; jj < 4; jj++) kr[jj] = Ks[(cg * 4 + jj) * QS_STRIDE + d];
#pragma unroll
            for (int ii = 0; ii < 4; ii++)
#pragma unroll
                for (int jj = 0; jj < 4; jj++)
                    sacc[ii][jj] = fmaf(qr[ii], kr[jj], sacc[ii][jj]);
        }
        const int gq0 = qb * 64, gk0 = kb * 64;
#pragma unroll
        for (int ii = 0; ii < 4; ii++)
#pragma unroll
            for (int jj = 0; jj < 4; jj++) {
                float s = sacc[ii][jj] * scale;
                if (gk0 + cg * 4 + jj > gq0 + ig * 4 + ii) s += -1e9f;
                Ss[(ig * 4 + ii) * SS_STRIDE + cg * 4 + jj] = s;
            }
        __syncthreads();

        if (tid < 64) {
            float m_old = mrow[tid];
            float m = m_old;
            for (int j = 0; j < 64; j++) m = fmaxf(m, Ss[tid * SS_STRIDE + j]);
            float sum = 0.f;
            for (int j = 0; j < 64; j++) {
                float p = __expf(Ss[tid * SS_STRIDE + j] - m);
                Ss[tid * SS_STRIDE + j] = p;
                sum += p;
            }
            float alpha = __expf(m_old - m);
            lrow[tid] = lrow[tid] * alpha + sum;
            mrow[tid] = m;
            arow[tid] = alpha;
        }
        __syncthreads();

#pragma unroll
        for (int ii = 0; ii < 4; ii++) {
            float a = arow[ig * 4 + ii];
#pragma unroll
            for (int c = 0; c < 8; c++) Oacc[ii][c] *= a;
        }
        for (int j = 0; j < 64; j++) {
            float4 v0 = *(const float4*)&Vs[j * VS_STRIDE + cg * 8];
            float4 v1 = *(const float4*)&Vs[j * VS_STRIDE + cg * 8 + 4];
            float vr[8] = {v0.x, v0.y, v0.z, v0.w, v1.x, v1.y, v1.z, v1.w};
            float p[4];
#pragma unroll
            for (int ii = 0; ii < 4; ii++) p[ii] = Ss[(ig * 4 + ii) * SS_STRIDE + j];
#pragma unroll
            for (int ii = 0; ii < 4; ii++)
#pragma unroll
                for (int c = 0; c < 8; c++) Oacc[ii][c] = fmaf(p[ii], vr[c], Oacc[ii][c]);
        }
    }

    size_t obase = (((size_t)(b * SEQLEN + qb * 64) * NHEADS) + h) * HDIM;
#pragma unroll
    for (int ii = 0; ii < 4; ii++) {
        int i = ig * 4 + ii;
        float inv = 1.f / lrow[i];
        float4 o0 = {Oacc[ii][0] * inv, Oacc[ii][1] * inv, Oacc[ii][2] * inv, Oacc[ii][3] * inv};
        float4 o1 = {Oacc[ii][4] * inv, Oacc[ii][5] * inv, Oacc[ii][6] * inv, Oacc[ii][7] * inv};
        float* Op = O + obase + (size_t)i * (NHEADS * HDIM) + cg * 8;
        *(float4*)(Op) = o0;
        *(float4*)(Op + 4) = o1;
    }
}

// ---------------------------------------------------------------------------
extern "C" void kernel_launch(void* const* d_in, const int* in_sizes, int n_in,
                              void* d_out, int out_size) {
    const float* x  = (const float*)d_in[0];
    const float* fc = (const float*)d_in[1];
    const float* wq = (const float*)d_in[4];
    const float* wk = (const float*)d_in[5];
    const float* wv = (const float*)d_in[6];
    const float* wo = (const float*)d_in[7];

    float* out = (float*)d_out;
    float* Kh = out + OUT_ELEMS;
    float* Vh = Kh + OUT_ELEMS;

    float *qbuf, *abuf;
    __nv_bfloat16 *xh, *xl, *wh, *wl, *ah, *al;
    cudaGetSymbolAddress((void**)&qbuf, g_Q);
    cudaGetSymbolAddress((void**)&abuf, g_attn);
    cudaGetSymbolAddress((void**)&xh, g_xh);
    cudaGetSymbolAddress((void**)&xl, g_xl);
    cudaGetSymbolAddress((void**)&wh, g_wh);
    cudaGetSymbolAddress((void**)&wl, g_wl);
    cudaGetSymbolAddress((void**)&ah, g_ah);
    cudaGetSymbolAddress((void**)&al, g_al);

    const size_t WSZ = (size_t)DIM * DIM;
    const int cblocks = (int)(WSZ / 4 / 256);

    convert_split<<<cblocks, 256>>>(x, xh, xl);
    convert_split<<<cblocks, 256>>>(wq, wh + 0 * WSZ, wl + 0 * WSZ);
    convert_split<<<cblocks, 256>>>(wk, wh + 1 * WSZ, wl + 1 * WSZ);
    convert_split<<<cblocks, 256>>>(wv, wh + 2 * WSZ, wl + 2 * WSZ);
    convert_split<<<cblocks, 256>>>(wo, wh + 3 * WSZ, wl + 3 * WSZ);

    cudaFuncSetAttribute(gemm_mma, cudaFuncAttributeMaxDynamicSharedMemorySize, GEMM_SMEM);
    dim3 ggrid(DIM / 128, NTOK / 128);
    gemm_mma<<<ggrid, 256, GEMM_SMEM>>>(xh, xl, wh + 0 * WSZ, wl + 0 * WSZ, qbuf);
    gemm_mma<<<ggrid, 256, GEMM_SMEM>>>(xh, xl, wh + 1 * WSZ, wl + 1 * WSZ, Kh);
    gemm_mma<<<ggrid, 256, GEMM_SMEM>>>(xh, xl, wh + 2 * WSZ, wl + 2 * WSZ, Vh);

    int rtotal = BSZ * SEQLEN * NHEADS * (HDIM / 2);
    rotary_kernel<<<(rtotal + 255) / 256, 256>>>(qbuf, Kh, fc);

    int smem = (64 * QS_STRIDE * 2 + 64 * VS_STRIDE + 64 * SS_STRIDE + 192) * sizeof(float);
    cudaFuncSetAttribute(attn_kernel, cudaFuncAttributeMaxDynamicSharedMemorySize, smem);
    attn_kernel<<<dim3(SEQLEN / 64, NHEADS, BSZ), 256, smem>>>(qbuf, Kh, Vh, abuf);

    convert_split<<<cblocks, 256>>>(abuf, ah, al);
    gemm_mma<<<ggrid, 256, GEMM_SMEM>>>(ah, al, wh + 3 * WSZ, wl + 3 * WSZ, out);
}

// round 4
// speedup vs baseline: 2.9615x; 1.4339x over previous
#include <cuda_runtime.h>
#include <cuda_bf16.h>
#include <cstdint>

#define BSZ 2
#define SEQLEN 2048
#define NHEADS 32
#define HDIM 128
#define DIM 4096
#define NTOK (BSZ * SEQLEN)              // 4096
#define OUT_ELEMS ((size_t)NTOK * DIM)   // 16,777,216

// ---------------- GEMM tiling ----------------
#define BK 32
#define CHUNKS (DIM / BK)                // 128
#define SSTRIDE 40                       // smem row stride in bf16 elems (80B)
#define MAT_B (128 * SSTRIDE * 2)        // 10240 B per matrix per stage
#define STAGE_B (4 * MAT_B)              // Ah, Al, Bh, Bl = 40960 B
#define NSTAGE 3
#define GEMM_SMEM (NSTAGE * STAGE_B)     // 122880 B

// ---------------- attention tiling ----------------
#define AQ_STRIDE 272                    // bytes per Q/K smem row (136 bf16)
#define AV_STRIDE 144                    // bytes per Vt smem row (72 bf16)
#define Q_BYTES (128 * AQ_STRIDE)        // 34816
#define K_BYTES (64 * AQ_STRIDE)         // 17408
#define VT_BYTES (128 * AV_STRIDE)       // 18432
#define KVBUF_BYTES (2 * K_BYTES + 2 * VT_BYTES)   // 71680
#define ATTN_SMEM (2 * Q_BYTES + 2 * KVBUF_BYTES)  // 212992

// ---------------- scratch (device globals; no allocation allowed) -----------
__device__ __align__(256) float g_Q[OUT_ELEMS];
__device__ __align__(256) __nv_bfloat16 g_xh[OUT_ELEMS];
__device__ __align__(256) __nv_bfloat16 g_xl[OUT_ELEMS];
__device__ __align__(256) __nv_bfloat16 g_wh[4ull * DIM * DIM];
__device__ __align__(256) __nv_bfloat16 g_wl[4ull * DIM * DIM];
__device__ __align__(256) __nv_bfloat16 g_ah[OUT_ELEMS];
__device__ __align__(256) __nv_bfloat16 g_al[OUT_ELEMS];
__device__ __align__(256) __nv_bfloat16 g_qh[OUT_ELEMS];
__device__ __align__(256) __nv_bfloat16 g_ql[OUT_ELEMS];
__device__ __align__(256) __nv_bfloat16 g_kh[OUT_ELEMS];
__device__ __align__(256) __nv_bfloat16 g_kl[OUT_ELEMS];
__device__ __align__(256) __nv_bfloat16 g_vth[OUT_ELEMS];
__device__ __align__(256) __nv_bfloat16 g_vtl[OUT_ELEMS];

// ---------------- PTX helpers ------------------------------------------------
__device__ __forceinline__ uint32_t smem_u32(const void* p) {
    uint32_t a;
    asm("{ .reg .u64 t; cvta.to.shared.u64 t, %1; cvt.u32.u64 %0, t; }" : "=r"(a) : "l"(p));
    return a;
}
__device__ __forceinline__ void cp16(uint32_t dst, const void* src) {
    asm volatile("cp.async.cg.shared.global [%0], [%1], 16;" :: "r"(dst), "l"(src));
}
__device__ __forceinline__ void ldsm4(uint32_t* r, uint32_t addr) {
    asm volatile("ldmatrix.sync.aligned.m8n8.x4.shared.b16 {%0,%1,%2,%3}, [%4];"
        : "=r"(r[0]), "=r"(r[1]), "=r"(r[2]), "=r"(r[3]) : "r"(addr));
}
__device__ __forceinline__ void mma16816(float* c, const uint32_t* a, const uint32_t* b) {
    asm volatile("mma.sync.aligned.m16n8k16.row.col.f32.bf16.bf16.f32 "
        "{%0,%1,%2,%3}, {%4,%5,%6,%7}, {%8,%9}, {%0,%1,%2,%3};"
        : "+f"(c[0]), "+f"(c[1]), "+f"(c[2]), "+f"(c[3])
        : "r"(a[0]), "r"(a[1]), "r"(a[2]), "r"(a[3]), "r"(b[0]), "r"(b[1]));
}
__device__ __forceinline__ void split2(float a, float b, uint32_t& hi, uint32_t& lo) {
    __nv_bfloat162 h = __floats2bfloat162_rn(a, b);
    float ra = a - __bfloat162float(h.x);
    float rb = b - __bfloat162float(h.y);
    __nv_bfloat162 l = __floats2bfloat162_rn(ra, rb);
    hi = *(uint32_t*)&h;
    lo = *(uint32_t*)&l;
}

// ---------------------------------------------------------------------------
// fp32 -> (bf16 hi, bf16 lo), plain row-major.
// ---------------------------------------------------------------------------
__global__ __launch_bounds__(256) void convert_split(const float* __restrict__ src,
                                                     __nv_bfloat16* __restrict__ hi,
                                                     __nv_bfloat16* __restrict__ lo) {
    size_t i = (size_t)blockIdx.x * blockDim.x + threadIdx.x;
    float4 v = ((const float4*)src)[i];
    float f[4] = {v.x, v.y, v.z, v.w};
    __nv_bfloat16 h4[4], l4[4];
#pragma unroll
    for (int j = 0; j < 4; j++) {
        h4[j] = __float2bfloat16(f[j]);
        l4[j] = __float2bfloat16(f[j] - __bfloat162float(h4[j]));
    }
    ((uint2*)hi)[i] = *(uint2*)h4;
    ((uint2*)lo)[i] = *(uint2*)l4;
}

// ---------------------------------------------------------------------------
// Split-bf16 mma.sync GEMM (unchanged from round 3)
// ---------------------------------------------------------------------------
__global__ __launch_bounds__(256)
void gemm_mma(const __nv_bfloat16* __restrict__ Ah, const __nv_bfloat16* __restrict__ Al,
              const __nv_bfloat16* __restrict__ Bh, const __nv_bfloat16* __restrict__ Bl,
              float* __restrict__ C) {
    extern __shared__ char sm_raw[];
    const uint32_t base = smem_u32(sm_raw);
    const int tid = threadIdx.x;
    const int warp = tid >> 5, lane = tid & 31;
    const int wm = warp & 1, wn = warp >> 1;
    const int nt = blockIdx.x, mt = blockIdx.y;

    const __nv_bfloat16* gsrc0 = Ah + (size_t)mt * 128 * DIM;
    const __nv_bfloat16* gsrc1 = Al + (size_t)mt * 128 * DIM;
    const __nv_bfloat16* gsrc2 = Bh + (size_t)nt * 128 * DIM;
    const __nv_bfloat16* gsrc3 = Bl + (size_t)nt * 128 * DIM;

#define LOAD_CHUNK(c, s)                                                         \
    do {                                                                         \
        const int ch_ = tid & 3;                                                 \
        _Pragma("unroll")                                                        \
        for (int i_ = 0; i_ < 8; i_++) {                                         \
            const int mat_ = i_ >> 1;                                            \
            const int r_ = (((i_ & 1) << 6) + (tid >> 2)) & 127;                 \
            uint32_t dst_ = base + (s) * STAGE_B + mat_ * MAT_B +                \
                            r_ * (SSTRIDE * 2) + ch_ * 16;                       \
            const __nv_bfloat16* sp_ =                                           \
                (mat_ == 0 ? gsrc0 : mat_ == 1 ? gsrc1 : mat_ == 2 ? gsrc2       \
                                                       : gsrc3);                 \
            cp16(dst_, sp_ + (size_t)r_ * DIM + (c) * BK + ch_ * 8);             \
        }                                                                        \
        asm volatile("cp.async.commit_group;" ::: "memory");                     \
    } while (0)

    LOAD_CHUNK(0, 0);
    LOAD_CHUNK(1, 1);

    const uint32_t aOff = (wm * 64 + (lane & 15)) * (SSTRIDE * 2) + ((lane >> 4) << 3) * 2;
    const uint32_t bOff = (wn * 32 + (lane & 7) + ((lane & 16) >> 1)) * (SSTRIDE * 2) + (lane & 8) * 2;

    float c[4][4][4];
#pragma unroll
    for (int mi = 0; mi < 4; mi++)
#pragma unroll
        for (int ni = 0; ni < 4; ni++)
#pragma unroll
            for (int j = 0; j < 4; j++) c[mi][ni][j] = 0.f;

    for (int ck = 0; ck < CHUNKS; ck++) {
        const int s = ck % 3;
        if (ck + 2 < CHUNKS) asm volatile("cp.async.wait_group 1;" ::: "memory");
        else                 asm volatile("cp.async.wait_group 0;" ::: "memory");
        __syncthreads();

        if (ck + 2 < CHUNKS) LOAD_CHUNK(ck + 2, (ck + 2) % 3);

        const uint32_t sb = base + s * STAGE_B;
        const uint32_t aHi = sb + aOff;
        const uint32_t aLo = sb + MAT_B + aOff;
        const uint32_t bHi = sb + 2 * MAT_B + bOff;
        const uint32_t bLo = sb + 3 * MAT_B + bOff;

#pragma unroll
        for (int kk = 0; kk < 2; kk++) {
            const uint32_t kb = kk * 32;
            uint32_t bh[8], bl[8];
            ldsm4(bh + 0, bHi + kb);
            ldsm4(bh + 4, bHi + kb + 16 * SSTRIDE * 2);
            ldsm4(bl + 0, bLo + kb);
            ldsm4(bl + 4, bLo + kb + 16 * SSTRIDE * 2);
#pragma unroll
            for (int mi = 0; mi < 4; mi++) {
                uint32_t ah[4], al[4];
                ldsm4(ah, aHi + kb + mi * 16 * SSTRIDE * 2);
                ldsm4(al, aLo + kb + mi * 16 * SSTRIDE * 2);
#pragma unroll
                for (int ni = 0; ni < 4; ni++) {
                    mma16816(c[mi][ni], ah, &bh[ni * 2]);
                    mma16816(c[mi][ni], al, &bh[ni * 2]);
                    mma16816(c[mi][ni], ah, &bl[ni * 2]);
                }
            }
        }
    }

    float* Cw = C + (size_t)(mt * 128 + wm * 64) * DIM + nt * 128 + wn * 32;
    const int cr = lane >> 2, cc = (lane & 3) * 2;
#pragma unroll
    for (int mi = 0; mi < 4; mi++)
#pragma unroll
        for (int ni = 0; ni < 4; ni++) {
            float* p0 = Cw + (size_t)(mi * 16 + cr) * DIM + ni * 8 + cc;
            float* p1 = p0 + 8 * DIM;
            *(float2*)p0 = make_float2(c[mi][ni][0], c[mi][ni][1]);
            *(float2*)p1 = make_float2(c[mi][ni][2], c[mi][ni][3]);
        }
}

// ---------------------------------------------------------------------------
// Rotary + bf16 split for Q (scaled by log2e/sqrt(d)) and K. Writes rotated K
// back to the fp32 hidden output, and Q/K bf16 hi/lo in [B,H,S,D] layout.
// ---------------------------------------------------------------------------
__global__ __launch_bounds__(256) void rotary_convert(
        const float* __restrict__ Q, float* __restrict__ Kf,
        const float* __restrict__ fc,
        __nv_bfloat16* __restrict__ qh, __nv_bfloat16* __restrict__ ql,
        __nv_bfloat16* __restrict__ kh, __nv_bfloat16* __restrict__ kl) {
    const float QSC = 1.44269504088896f / 11.3137084989848f;  // log2e / sqrt(128)
    int idx = blockIdx.x * blockDim.x + threadIdx.x;
    int p = idx & 63;
    int h = (idx >> 6) & 31;
    int s = (idx >> 11) & (SEQLEN - 1);
    int b = idx >> 22;

    float c = fc[(s * 64 + p) * 2];
    float sn = fc[(s * 64 + p) * 2 + 1];

    size_t in = (((size_t)(b * SEQLEN + s) * NHEADS) + h) * HDIM + p * 2;
    size_t out = (((size_t)(b * NHEADS + h) * SEQLEN) + s) * HDIM + p * 2;

    float2 q = *(float2*)(Q + in);
    float2 k = *(float2*)(Kf + in);
    float2 qo = {q.x * c - q.y * sn, q.x * sn + q.y * c};
    float2 ko = {k.x * c - k.y * sn, k.x * sn + k.y * c};
    *(float2*)(Kf + in) = ko;

    uint32_t hi, lo;
    split2(qo.x * QSC, qo.y * QSC, hi, lo);
    *(uint32_t*)(qh + out) = hi;
    *(uint32_t*)(ql + out) = lo;
    split2(ko.x, ko.y, hi, lo);
    *(uint32_t*)(kh + out) = hi;
    *(uint32_t*)(kl + out) = lo;
}

// ---------------------------------------------------------------------------
// V transpose + split: fp32 [B,S,H,D] -> bf16 hi/lo [B,H,D,S]
// ---------------------------------------------------------------------------
__global__ __launch_bounds__(256) void v_transpose(const float* __restrict__ V,
                                                   __nv_bfloat16* __restrict__ vth,
                                                   __nv_bfloat16* __restrict__ vtl) {
    __shared__ float t[32][33];
    int s0 = blockIdx.x * 32, d0 = blockIdx.y * 32;
    int bh = blockIdx.z;
    int b = bh >> 5, h = bh & 31;
#pragma unroll
    for (int i = 0; i < 4; i++) {
        int s = s0 + threadIdx.y + i * 8;
        t[threadIdx.y + i * 8][threadIdx.x] =
            V[(((size_t)(b * SEQLEN + s) * NHEADS) + h) * HDIM + d0 + threadIdx.x];
    }
    __syncthreads();
#pragma unroll
    for (int i = 0; i < 4; i++) {
        int d = d0 + threadIdx.y + i * 8;
        float v = t[threadIdx.x][threadIdx.y + i * 8];
        __nv_bfloat16 hb = __float2bfloat16(v);
        size_t o = ((size_t)bh * HDIM + d) * SEQLEN + s0 + threadIdx.x;
        vth[o] = hb;
        vtl[o] = __float2bfloat16(v - __bfloat162float(hb));
    }
}

// ---------------------------------------------------------------------------
// Flash attention, split-bf16 mma.sync. CTA: 128 q-rows x (head, batch).
// 8 warps, warp owns 16 q-rows. K-tile 64, double-buffered cp.async.
// Output written directly as bf16 hi/lo [token][dim] for the Wo GEMM.
// ---------------------------------------------------------------------------
__global__ __launch_bounds__(256)
void flash_attn(const __nv_bfloat16* __restrict__ Qh, const __nv_bfloat16* __restrict__ Ql,
                const __nv_bfloat16* __restrict__ Kbh, const __nv_bfloat16* __restrict__ Kbl,
                const __nv_bfloat16* __restrict__ Vth, const __nv_bfloat16* __restrict__ Vtl,
                __nv_bfloat16* __restrict__ Oh, __nv_bfloat16* __restrict__ Ol) {
    extern __shared__ char sm_raw[];
    const uint32_t base = smem_u32(sm_raw);
    const int tid = threadIdx.x, warp = tid >> 5, lane = tid & 31;
    const int qt = blockIdx.x, h = blockIdx.y, b = blockIdx.z;
    const size_t bhd = (size_t)(b * NHEADS + h);

    const uint32_t sQh = base, sQl = base + Q_BYTES;
    const uint32_t sKV = base + 2 * Q_BYTES;

    // load Q tile (group 0, together with first K/V tile)
    {
        const char* gq = (const char*)(Qh + (bhd * SEQLEN + qt * 128) * HDIM);
        const char* gl = (const char*)(Ql + (bhd * SEQLEN + qt * 128) * HDIM);
        int row = tid >> 4, ch = tid & 15;
#pragma unroll
        for (int i = 0; i < 8; i++) {
            int r = row + i * 16;
            cp16(sQh + r * AQ_STRIDE + ch * 16, gq + r * 256 + ch * 16);
            cp16(sQl + r * AQ_STRIDE + ch * 16, gl + r * 256 + ch * 16);
        }
    }

#define LOADKV(kb_, p_)                                                              \
    do {                                                                             \
        uint32_t kvb_ = sKV + (p_) * KVBUF_BYTES;                                    \
        const char* gkh_ = (const char*)(Kbh + (bhd * SEQLEN + (kb_) * 64) * HDIM);  \
        const char* gkl_ = (const char*)(Kbl + (bhd * SEQLEN + (kb_) * 64) * HDIM);  \
        {                                                                            \
            int row_ = tid >> 4, ch_ = tid & 15;                                     \
            _Pragma("unroll")                                                        \
            for (int i_ = 0; i_ < 4; i_++) {                                         \
                int r_ = row_ + i_ * 16;                                             \
                cp16(kvb_ + r_ * AQ_STRIDE + ch_ * 16, gkh_ + r_ * 256 + ch_ * 16);  \
                cp16(kvb_ + K_BYTES + r_ * AQ_STRIDE + ch_ * 16,                     \
                     gkl_ + r_ * 256 + ch_ * 16);                                    \
            }                                                                        \
        }                                                                            \
        const char* gvh_ = (const char*)(Vth + bhd * HDIM * SEQLEN + (kb_) * 64);    \
        const char* gvl_ = (const char*)(Vtl + bhd * HDIM * SEQLEN + (kb_) * 64);    \
        {                                                                            \
            int row_ = tid >> 3, ch_ = tid & 7;                                      \
            _Pragma("unroll")                                                        \
            for (int i_ = 0; i_ < 4; i_++) {                                         \
                int r_ = row_ + i_ * 32;                                             \
                cp16(kvb_ + 2 * K_BYTES + r_ * AV_STRIDE + ch_ * 16,                 \
                     gvh_ + (size_t)r_ * SEQLEN * 2 + ch_ * 16);                     \
                cp16(kvb_ + 2 * K_BYTES + VT_BYTES + r_ * AV_STRIDE + ch_ * 16,      \
                     gvl_ + (size_t)r_ * SEQLEN * 2 + ch_ * 16);                     \
            }                                                                        \
        }                                                                            \
        asm volatile("cp.async.commit_group;" ::: "memory");                         \
    } while (0)

    const int nt = 2 * qt + 2;
    LOADKV(0, 0);
    LOADKV(1, 1);

    const uint32_t aQoff = (warp * 16 + (lane & 15)) * AQ_STRIDE + ((lane >> 4) << 4);
    const uint32_t bKoff = ((lane & 7) + ((lane & 16) >> 1)) * AQ_STRIDE + (lane & 8) * 2;
    const uint32_t bVoff = ((lane & 7) + ((lane & 16) >> 1)) * AV_STRIDE + (lane & 8) * 2;

    float o[16][4];
#pragma unroll
    for (int j = 0; j < 16; j++)
#pragma unroll
        for (int c = 0; c < 4; c++) o[j][c] = 0.f;
    float m_run[2] = {-1e30f, -1e30f}, l_run[2] = {0.f, 0.f};

    for (int kb = 0; kb < nt; kb++) {
        const uint32_t kvb = sKV + (kb & 1) * KVBUF_BYTES;
        if (kb + 1 < nt) asm volatile("cp.async.wait_group 1;" ::: "memory");
        else             asm volatile("cp.async.wait_group 0;" ::: "memory");
        __syncthreads();

        // ---- S = Q @ K^T (3 split terms) ----
        float s[8][4];
#pragma unroll
        for (int j = 0; j < 8; j++)
#pragma unroll
            for (int c = 0; c < 4; c++) s[j][c] = 0.f;

#pragma unroll
        for (int ks = 0; ks < 8; ks++) {
            uint32_t ah[4], al[4];
            ldsm4(ah, sQh + aQoff + ks * 32);
            ldsm4(al, sQl + aQoff + ks * 32);
#pragma unroll
            for (int nb = 0; nb < 4; nb++) {
                uint32_t kh4[4], kl4[4];
                ldsm4(kh4, kvb + bKoff + nb * 16 * AQ_STRIDE + ks * 32);
                ldsm4(kl4, kvb + K_BYTES + bKoff + nb * 16 * AQ_STRIDE + ks * 32);
                mma16816(s[nb * 2], ah, kh4);
                mma16816(s[nb * 2], al, kh4);
                mma16816(s[nb * 2], ah, kl4);
                mma16816(s[nb * 2 + 1], ah, kh4 + 2);
                mma16816(s[nb * 2 + 1], al, kh4 + 2);
                mma16816(s[nb * 2 + 1], ah, kl4 + 2);
            }
        }

        // ---- causal mask (only last two tiles can clip) ----
        if (kb >= 2 * qt) {
            int r0 = qt * 128 + warp * 16 + (lane >> 2);
            int c0 = kb * 64 + (lane & 3) * 2;
#pragma unroll
            for (int j = 0; j < 8; j++)
#pragma unroll
                for (int c = 0; c < 4; c++) {
                    int col = c0 + j * 8 + (c & 1);
                    int row = r0 + ((c & 2) ? 8 : 0);
                    if (col > row) s[j][c] = -1e30f;
                }
        }

        // ---- online softmax (warp-local; rows split in lane quads) ----
        float mloc[2] = {-1e30f, -1e30f};
#pragma unroll
        for (int j = 0; j < 8; j++) {
            mloc[0] = fmaxf(mloc[0], fmaxf(s[j][0], s[j][1]));
            mloc[1] = fmaxf(mloc[1], fmaxf(s[j][2], s[j][3]));
        }
        float mnew[2], alpha[2], rs[2];
#pragma unroll
        for (int h2 = 0; h2 < 2; h2++) {
            mloc[h2] = fmaxf(mloc[h2], __shfl_xor_sync(0xffffffffu, mloc[h2], 1));
            mloc[h2] = fmaxf(mloc[h2], __shfl_xor_sync(0xffffffffu, mloc[h2], 2));
            mnew[h2] = fmaxf(m_run[h2], mloc[h2]);
            alpha[h2] = exp2f(m_run[h2] - mnew[h2]);
            rs[h2] = 0.f;
        }
#pragma unroll
        for (int j = 0; j < 8; j++) {
            s[j][0] = exp2f(s[j][0] - mnew[0]);
            s[j][1] = exp2f(s[j][1] - mnew[0]);
            s[j][2] = exp2f(s[j][2] - mnew[1]);
            s[j][3] = exp2f(s[j][3] - mnew[1]);
            rs[0] += s[j][0] + s[j][1];
            rs[1] += s[j][2] + s[j][3];
        }
#pragma unroll
        for (int h2 = 0; h2 < 2; h2++) {
            rs[h2] += __shfl_xor_sync(0xffffffffu, rs[h2], 1);
            rs[h2] += __shfl_xor_sync(0xffffffffu, rs[h2], 2);
            l_run[h2] = l_run[h2] * alpha[h2] + rs[h2];
            m_run[h2] = mnew[h2];
        }
#pragma unroll
        for (int j = 0; j < 16; j++) {
            o[j][0] *= alpha[0];
            o[j][1] *= alpha[0];
            o[j][2] *= alpha[1];
            o[j][3] *= alpha[1];
        }

        // ---- O += P @ V (3 split terms); P frag from S registers ----
#pragma unroll
        for (int kc = 0; kc < 4; kc++) {
            uint32_t pah[4], pal[4];
            split2(s[2 * kc][0], s[2 * kc][1], pah[0], pal[0]);
            split2(s[2 * kc][2], s[2 * kc][3], pah[1], pal[1]);
            split2(s[2 * kc + 1][0], s[2 * kc + 1][1], pah[2], pal[2]);
            split2(s[2 * kc + 1][2], s[2 * kc + 1][3], pah[3], pal[3]);
#pragma unroll
            for (int nb = 0; nb < 8; nb++) {
                uint32_t vh4[4], vl4[4];
                ldsm4(vh4, kvb + 2 * K_BYTES + bVoff + nb * 16 * AV_STRIDE + kc * 32);
                ldsm4(vl4, kvb + 2 * K_BYTES + VT_BYTES + bVoff + nb * 16 * AV_STRIDE + kc * 32);
                mma16816(o[nb * 2], pah, vh4);
                mma16816(o[nb * 2], pal, vh4);
                mma16816(o[nb * 2], pah, vl4);
                mma16816(o[nb * 2 + 1], pah, vh4 + 2);
                mma16816(o[nb * 2 + 1], pal, vh4 + 2);
                mma16816(o[nb * 2 + 1], pah, vl4 + 2);
            }
        }

        if (kb + 2 < nt) {
            __syncthreads();
            LOADKV(kb + 2, kb & 1);
        }
    }

    // ---- normalize + write bf16 hi/lo [token][dim] ----
    float inv[2] = {1.f / l_run[0], 1.f / l_run[1]};
    size_t trow = (size_t)b * SEQLEN + qt * 128 + warp * 16 + (lane >> 2);
#pragma unroll
    for (int j = 0; j < 16; j++) {
        int c0 = j * 8 + (lane & 3) * 2;
#pragma unroll
        for (int h2 = 0; h2 < 2; h2++) {
            size_t t = trow + h2 * 8;
            float v0 = o[j][h2 * 2] * inv[h2];
            float v1 = o[j][h2 * 2 + 1] * inv[h2];
            uint32_t hi, lo;
            split2(v0, v1, hi, lo);
            *(uint32_t*)(Oh + t * DIM + h * HDIM + c0) = hi;
            *(uint32_t*)(Ol + t * DIM + h * HDIM + c0) = lo;
        }
    }
}

// ---------------------------------------------------------------------------
extern "C" void kernel_launch(void* const* d_in, const int* in_sizes, int n_in,
                              void* d_out, int out_size) {
    const float* x  = (const float*)d_in[0];
    const float* fc = (const float*)d_in[1];
    const float* wq = (const float*)d_in[4];
    const float* wk = (const float*)d_in[5];
    const float* wv = (const float*)d_in[6];
    const float* wo = (const float*)d_in[7];

    float* out = (float*)d_out;
    float* Kh = out + OUT_ELEMS;
    float* Vh = Kh + OUT_ELEMS;

    float* qbuf;
    __nv_bfloat16 *xh, *xl, *wh, *wl, *ah, *al, *qh, *ql, *kbh, *kbl, *vth, *vtl;
    cudaGetSymbolAddress((void**)&qbuf, g_Q);
    cudaGetSymbolAddress((void**)&xh, g_xh);
    cudaGetSymbolAddress((void**)&xl, g_xl);
    cudaGetSymbolAddress((void**)&wh, g_wh);
    cudaGetSymbolAddress((void**)&wl, g_wl);
    cudaGetSymbolAddress((void**)&ah, g_ah);
    cudaGetSymbolAddress((void**)&al, g_al);
    cudaGetSymbolAddress((void**)&qh, g_qh);
    cudaGetSymbolAddress((void**)&ql, g_ql);
    cudaGetSymbolAddress((void**)&kbh, g_kh);
    cudaGetSymbolAddress((void**)&kbl, g_kl);
    cudaGetSymbolAddress((void**)&vth, g_vth);
    cudaGetSymbolAddress((void**)&vtl, g_vtl);

    const size_t WSZ = (size_t)DIM * DIM;
    const int cblocks = (int)(WSZ / 4 / 256);

    convert_split<<<cblocks, 256>>>(x, xh, xl);
    convert_split<<<cblocks, 256>>>(wq, wh + 0 * WSZ, wl + 0 * WSZ);
    convert_split<<<cblocks, 256>>>(wk, wh + 1 * WSZ, wl + 1 * WSZ);
    convert_split<<<cblocks, 256>>>(wv, wh + 2 * WSZ, wl + 2 * WSZ);
    convert_split<<<cblocks, 256>>>(wo, wh + 3 * WSZ, wl + 3 * WSZ);

    cudaFuncSetAttribute(gemm_mma, cudaFuncAttributeMaxDynamicSharedMemorySize, GEMM_SMEM);
    dim3 ggrid(DIM / 128, NTOK / 128);
    gemm_mma<<<ggrid, 256, GEMM_SMEM>>>(xh, xl, wh + 0 * WSZ, wl + 0 * WSZ, qbuf);
    gemm_mma<<<ggrid, 256, GEMM_SMEM>>>(xh, xl, wh + 1 * WSZ, wl + 1 * WSZ, Kh);
    gemm_mma<<<ggrid, 256, GEMM_SMEM>>>(xh, xl, wh + 2 * WSZ, wl + 2 * WSZ, Vh);

    int rtotal = BSZ * SEQLEN * NHEADS * (HDIM / 2);
    rotary_convert<<<rtotal / 256, 256>>>(qbuf, Kh, fc, qh, ql, kbh, kbl);
    v_transpose<<<dim3(SEQLEN / 32, HDIM / 32, BSZ * NHEADS), dim3(32, 8)>>>(Vh, vth, vtl);

    cudaFuncSetAttribute(flash_attn, cudaFuncAttributeMaxDynamicSharedMemorySize, ATTN_SMEM);
    flash_attn<<<dim3(SEQLEN / 128, NHEADS, BSZ), 256, ATTN_SMEM>>>(
        qh, ql, kbh, kbl, vth, vtl, ah, al);

    gemm_mma<<<ggrid, 256, GEMM_SMEM>>>(ah, al, wh + 3 * WSZ, wl + 3 * WSZ, out);
}

// round 5
// speedup vs baseline: 3.1384x; 1.0597x over previous
#include <cuda_runtime.h>
#include <cuda_bf16.h>
#include <cstdint>

#define BSZ 2
#define SEQLEN 2048
#define NHEADS 32
#define HDIM 128
#define DIM 4096
#define NTOK (BSZ * SEQLEN)              // 4096
#define OUT_ELEMS ((size_t)NTOK * DIM)   // 16,777,216

// ---------------- GEMM tiling: 256x128 CTA tile, BK=32 ----------------
#define BK 32
#define CHUNKS (DIM / BK)                // 128
#define SROW 80                          // smem row stride bytes (40 bf16)
#define MAT_A_B (256 * SROW)             // 20480
#define MAT_B_B (128 * SROW)             // 10240
#define STAGE_B (2 * MAT_A_B + 2 * MAT_B_B)   // 61440
#define NSTAGE 3
#define GEMM_SMEM (NSTAGE * STAGE_B)     // 184320 B

// ---------------- attention tiling ----------------
#define AQ_STRIDE 272                    // bytes per Q/K smem row (136 bf16)
#define AV_STRIDE 144                    // bytes per Vt smem row (72 bf16)
#define Q_BYTES (128 * AQ_STRIDE)        // 34816
#define K_BYTES (64 * AQ_STRIDE)         // 17408
#define VT_BYTES (128 * AV_STRIDE)       // 18432
#define KVBUF_BYTES (2 * K_BYTES + 2 * VT_BYTES)   // 71680
#define ATTN_SMEM (2 * Q_BYTES + 2 * KVBUF_BYTES)  // 212992

// ---------------- scratch (device globals; no allocation allowed) -----------
__device__ __align__(256) float g_Q[OUT_ELEMS];
__device__ __align__(256) __nv_bfloat16 g_xh[OUT_ELEMS];
__device__ __align__(256) __nv_bfloat16 g_xl[OUT_ELEMS];
__device__ __align__(256) __nv_bfloat16 g_wh[4ull * DIM * DIM];
__device__ __align__(256) __nv_bfloat16 g_wl[4ull * DIM * DIM];
__device__ __align__(256) __nv_bfloat16 g_ah[OUT_ELEMS];
__device__ __align__(256) __nv_bfloat16 g_al[OUT_ELEMS];
__device__ __align__(256) __nv_bfloat16 g_qh[OUT_ELEMS];
__device__ __align__(256) __nv_bfloat16 g_ql[OUT_ELEMS];
__device__ __align__(256) __nv_bfloat16 g_kh[OUT_ELEMS];
__device__ __align__(256) __nv_bfloat16 g_kl[OUT_ELEMS];
__device__ __align__(256) __nv_bfloat16 g_vth[OUT_ELEMS];
__device__ __align__(256) __nv_bfloat16 g_vtl[OUT_ELEMS];

// ---------------- PTX helpers ------------------------------------------------
__device__ __forceinline__ uint32_t smem_u32(const void* p) {
    uint32_t a;
    asm("{ .reg .u64 t; cvta.to.shared.u64 t, %1; cvt.u32.u64 %0, t; }" : "=r"(a) : "l"(p));
    return a;
}
__device__ __forceinline__ void cp16(uint32_t dst, const void* src) {
    asm volatile("cp.async.cg.shared.global [%0], [%1], 16;" :: "r"(dst), "l"(src));
}
__device__ __forceinline__ void ldsm4(uint32_t* r, uint32_t addr) {
    asm volatile("ldmatrix.sync.aligned.m8n8.x4.shared.b16 {%0,%1,%2,%3}, [%4];"
        : "=r"(r[0]), "=r"(r[1]), "=r"(r[2]), "=r"(r[3]) : "r"(addr));
}
__device__ __forceinline__ void mma16816(float* c, const uint32_t* a, const uint32_t* b) {
    asm volatile("mma.sync.aligned.m16n8k16.row.col.f32.bf16.bf16.f32 "
        "{%0,%1,%2,%3}, {%4,%5,%6,%7}, {%8,%9}, {%0,%1,%2,%3};"
        : "+f"(c[0]), "+f"(c[1]), "+f"(c[2]), "+f"(c[3])
        : "r"(a[0]), "r"(a[1]), "r"(a[2]), "r"(a[3]), "r"(b[0]), "r"(b[1]));
}
__device__ __forceinline__ void split2(float a, float b, uint32_t& hi, uint32_t& lo) {
    __nv_bfloat162 h = __floats2bfloat162_rn(a, b);
    float ra = a - __bfloat162float(h.x);
    float rb = b - __bfloat162float(h.y);
    __nv_bfloat162 l = __floats2bfloat162_rn(ra, rb);
    hi = *(uint32_t*)&h;
    lo = *(uint32_t*)&l;
}

// ---------------------------------------------------------------------------
// fp32 -> (bf16 hi, bf16 lo), plain row-major.
// ---------------------------------------------------------------------------
__global__ __launch_bounds__(256) void convert_split(const float* __restrict__ src,
                                                     __nv_bfloat16* __restrict__ hi,
                                                     __nv_bfloat16* __restrict__ lo) {
    size_t i = (size_t)blockIdx.x * blockDim.x + threadIdx.x;
    float4 v = ((const float4*)src)[i];
    float f[4] = {v.x, v.y, v.z, v.w};
    __nv_bfloat16 h4[4], l4[4];
#pragma unroll
    for (int j = 0; j < 4; j++) {
        h4[j] = __float2bfloat16(f[j]);
        l4[j] = __float2bfloat16(f[j] - __bfloat162float(h4[j]));
    }
    ((uint2*)hi)[i] = *(uint2*)h4;
    ((uint2*)lo)[i] = *(uint2*)l4;
}

// ---------------------------------------------------------------------------
// Split-bf16 mma.sync GEMM: C[m][n] = sum_k A[m][k]*B[n][k]  (both row-major)
// 256x128 CTA tile, BK=32, 3-stage cp.async, 8 warps of 64x64.
// Output routed to C0/C1/C2 by nt>>5 (fused QKV projection).
// ---------------------------------------------------------------------------
__global__ __launch_bounds__(256)
void gemm_mma(const __nv_bfloat16* __restrict__ Ah, const __nv_bfloat16* __restrict__ Al,
              const __nv_bfloat16* __restrict__ Bh, const __nv_bfloat16* __restrict__ Bl,
              float* __restrict__ C0, float* __restrict__ C1, float* __restrict__ C2) {
    extern __shared__ char sm_raw[];
    const uint32_t base = smem_u32(sm_raw);
    const int tid = threadIdx.x;
    const int warp = tid >> 5, lane = tid & 31;
    const int wm = warp & 3, wn = warp >> 2;     // 4 x 2 warp grid, warp 64x64
    const int nt = blockIdx.x, mt = blockIdx.y;

    const __nv_bfloat16* gA0 = Ah + (size_t)mt * 256 * DIM;
    const __nv_bfloat16* gA1 = Al + (size_t)mt * 256 * DIM;
    const __nv_bfloat16* gB0 = Bh + (size_t)nt * 128 * DIM;
    const __nv_bfloat16* gB1 = Bl + (size_t)nt * 128 * DIM;

#define LOAD_CHUNK(c, s)                                                         \
    do {                                                                         \
        const int ch_ = tid & 3;                                                 \
        const int r_ = tid >> 2;                                                 \
        const uint32_t st_ = base + (s) * STAGE_B;                               \
        const size_t ko_ = (size_t)(c) * BK + ch_ * 8;                           \
        _Pragma("unroll")                                                        \
        for (int i_ = 0; i_ < 4; i_++) {                                         \
            const int row_ = r_ + i_ * 64;                                       \
            cp16(st_ + row_ * SROW + ch_ * 16, gA0 + (size_t)row_ * DIM + ko_);  \
            cp16(st_ + MAT_A_B + row_ * SROW + ch_ * 16,                         \
                 gA1 + (size_t)row_ * DIM + ko_);                                \
        }                                                                        \
        _Pragma("unroll")                                                        \
        for (int i_ = 0; i_ < 2; i_++) {                                         \
            const int row_ = r_ + i_ * 64;                                       \
            cp16(st_ + 2 * MAT_A_B + row_ * SROW + ch_ * 16,                     \
                 gB0 + (size_t)row_ * DIM + ko_);                                \
            cp16(st_ + 2 * MAT_A_B + MAT_B_B + row_ * SROW + ch_ * 16,           \
                 gB1 + (size_t)row_ * DIM + ko_);                                \
        }                                                                        \
        asm volatile("cp.async.commit_group;" ::: "memory");                     \
    } while (0)

    LOAD_CHUNK(0, 0);
    LOAD_CHUNK(1, 1);

    const uint32_t aOff = (wm * 64 + (lane & 15)) * SROW + ((lane >> 4) << 4);
    const uint32_t bOff = (wn * 64 + (lane & 7) + ((lane & 16) >> 1)) * SROW + (lane & 8) * 2;

    float c[4][8][4];
#pragma unroll
    for (int mi = 0; mi < 4; mi++)
#pragma unroll
        for (int ni = 0; ni < 8; ni++)
#pragma unroll
            for (int j = 0; j < 4; j++) c[mi][ni][j] = 0.f;

    for (int ck = 0; ck < CHUNKS; ck++) {
        const int s = ck % 3;
        if (ck + 2 < CHUNKS) asm volatile("cp.async.wait_group 1;" ::: "memory");
        else                 asm volatile("cp.async.wait_group 0;" ::: "memory");
        __syncthreads();

        if (ck + 2 < CHUNKS) LOAD_CHUNK(ck + 2, (ck + 2) % 3);

        const uint32_t sb = base + s * STAGE_B;
        const uint32_t aHi = sb + aOff;
        const uint32_t aLo = sb + MAT_A_B + aOff;
        const uint32_t bHi = sb + 2 * MAT_A_B + bOff;
        const uint32_t bLo = sb + 2 * MAT_A_B + MAT_B_B + bOff;

#pragma unroll
        for (int kk = 0; kk < 2; kk++) {
            const uint32_t kb = kk * 32;   // 16 elems * 2B
            uint32_t bh[16], bl[16];
#pragma unroll
            for (int g = 0; g < 4; g++) {
                ldsm4(bh + g * 4, bHi + kb + g * 16 * SROW);
                ldsm4(bl + g * 4, bLo + kb + g * 16 * SROW);
            }
#pragma unroll
            for (int mi = 0; mi < 4; mi++) {
                uint32_t ah[4], al[4];
                ldsm4(ah, aHi + kb + mi * 16 * SROW);
                ldsm4(al, aLo + kb + mi * 16 * SROW);
#pragma unroll
                for (int ni = 0; ni < 8; ni++) {
                    mma16816(c[mi][ni], ah, &bh[ni * 2]);
                    mma16816(c[mi][ni], al, &bh[ni * 2]);
                    mma16816(c[mi][ni], ah, &bl[ni * 2]);
                }
            }
        }
    }

    // epilogue: route by nt>>5 (fused QKV), col block = (nt & 31) * 128
    float* Cb = (nt < 32) ? C0 : (nt < 64) ? C1 : C2;
    float* Cw = Cb + (size_t)(mt * 256 + wm * 64) * DIM + (nt & 31) * 128 + wn * 64;
    const int cr = lane >> 2, cc = (lane & 3) * 2;
#pragma unroll
    for (int mi = 0; mi < 4; mi++)
#pragma unroll
        for (int ni = 0; ni < 8; ni++) {
            float* p0 = Cw + (size_t)(mi * 16 + cr) * DIM + ni * 8 + cc;
            float* p1 = p0 + 8 * DIM;
            *(float2*)p0 = make_float2(c[mi][ni][0], c[mi][ni][1]);
            *(float2*)p1 = make_float2(c[mi][ni][2], c[mi][ni][3]);
        }
}

// ---------------------------------------------------------------------------
// Rotary + bf16 split for Q (scaled by log2e/sqrt(d)) and K. Writes rotated K
// back to the fp32 hidden output, and Q/K bf16 hi/lo in [B,H,S,D] layout.
// ---------------------------------------------------------------------------
__global__ __launch_bounds__(256) void rotary_convert(
        const float* __restrict__ Q, float* __restrict__ Kf,
        const float* __restrict__ fc,
        __nv_bfloat16* __restrict__ qh, __nv_bfloat16* __restrict__ ql,
        __nv_bfloat16* __restrict__ kh, __nv_bfloat16* __restrict__ kl) {
    const float QSC = 1.44269504088896f / 11.3137084989848f;  // log2e / sqrt(128)
    int idx = blockIdx.x * blockDim.x + threadIdx.x;
    int p = idx & 63;
    int h = (idx >> 6) & 31;
    int s = (idx >> 11) & (SEQLEN - 1);
    int b = idx >> 22;

    float c = fc[(s * 64 + p) * 2];
    float sn = fc[(s * 64 + p) * 2 + 1];

    size_t in = (((size_t)(b * SEQLEN + s) * NHEADS) + h) * HDIM + p * 2;
    size_t out = (((size_t)(b * NHEADS + h) * SEQLEN) + s) * HDIM + p * 2;

    float2 q = *(float2*)(Q + in);
    float2 k = *(float2*)(Kf + in);
    float2 qo = {q.x * c - q.y * sn, q.x * sn + q.y * c};
    float2 ko = {k.x * c - k.y * sn, k.x * sn + k.y * c};
    *(float2*)(Kf + in) = ko;

    uint32_t hi, lo;
    split2(qo.x * QSC, qo.y * QSC, hi, lo);
    *(uint32_t*)(qh + out) = hi;
    *(uint32_t*)(ql + out) = lo;
    split2(ko.x, ko.y, hi, lo);
    *(uint32_t*)(kh + out) = hi;
    *(uint32_t*)(kl + out) = lo;
}

// ---------------------------------------------------------------------------
// V transpose + split: fp32 [B,S,H,D] -> bf16 hi/lo [B,H,D,S]
// ---------------------------------------------------------------------------
__global__ __launch_bounds__(256) void v_transpose(const float* __restrict__ V,
                                                   __nv_bfloat16* __restrict__ vth,
                                                   __nv_bfloat16* __restrict__ vtl) {
    __shared__ float t[32][33];
    int s0 = blockIdx.x * 32, d0 = blockIdx.y * 32;
    int bh = blockIdx.z;
    int b = bh >> 5, h = bh & 31;
#pragma unroll
    for (int i = 0; i < 4; i++) {
        int s = s0 + threadIdx.y + i * 8;
        t[threadIdx.y + i * 8][threadIdx.x] =
            V[(((size_t)(b * SEQLEN + s) * NHEADS) + h) * HDIM + d0 + threadIdx.x];
    }
    __syncthreads();
#pragma unroll
    for (int i = 0; i < 4; i++) {
        int d = d0 + threadIdx.y + i * 8;
        float v = t[threadIdx.x][threadIdx.y + i * 8];
        __nv_bfloat16 hb = __float2bfloat16(v);
        size_t o = ((size_t)bh * HDIM + d) * SEQLEN + s0 + threadIdx.x;
        vth[o] = hb;
        vtl[o] = __float2bfloat16(v - __bfloat162float(hb));
    }
}

// ---------------------------------------------------------------------------
// Flash attention, split-bf16 mma.sync (unchanged from round 4).
// ---------------------------------------------------------------------------
__global__ __launch_bounds__(256)
void flash_attn(const __nv_bfloat16* __restrict__ Qh, const __nv_bfloat16* __restrict__ Ql,
                const __nv_bfloat16* __restrict__ Kbh, const __nv_bfloat16* __restrict__ Kbl,
                const __nv_bfloat16* __restrict__ Vth, const __nv_bfloat16* __restrict__ Vtl,
                __nv_bfloat16* __restrict__ Oh, __nv_bfloat16* __restrict__ Ol) {
    extern __shared__ char sm_raw[];
    const uint32_t base = smem_u32(sm_raw);
    const int tid = threadIdx.x, warp = tid >> 5, lane = tid & 31;
    const int qt = blockIdx.x, h = blockIdx.y, b = blockIdx.z;
    const size_t bhd = (size_t)(b * NHEADS + h);

    const uint32_t sQh = base, sQl = base + Q_BYTES;
    const uint32_t sKV = base + 2 * Q_BYTES;

    {
        const char* gq = (const char*)(Qh + (bhd * SEQLEN + qt * 128) * HDIM);
        const char* gl = (const char*)(Ql + (bhd * SEQLEN + qt * 128) * HDIM);
        int row = tid >> 4, ch = tid & 15;
#pragma unroll
        for (int i = 0; i < 8; i++) {
            int r = row + i * 16;
            cp16(sQh + r * AQ_STRIDE + ch * 16, gq + r * 256 + ch * 16);
            cp16(sQl + r * AQ_STRIDE + ch * 16, gl + r * 256 + ch * 16);
        }
    }

#define LOADKV(kb_, p_)                                                              \
    do {                                                                             \
        uint32_t kvb_ = sKV + (p_) * KVBUF_BYTES;                                    \
        const char* gkh_ = (const char*)(Kbh + (bhd * SEQLEN + (kb_) * 64) * HDIM);  \
        const char* gkl_ = (const char*)(Kbl + (bhd * SEQLEN + (kb_) * 64) * HDIM);  \
        {                                                                            \
            int row_ = tid >> 4, ch_ = tid & 15;                                     \
            _Pragma("unroll")                                                        \
            for (int i_ = 0; i_ < 4; i_++) {                                         \
                int r_ = row_ + i_ * 16;                                             \
                cp16(kvb_ + r_ * AQ_STRIDE + ch_ * 16, gkh_ + r_ * 256 + ch_ * 16);  \
                cp16(kvb_ + K_BYTES + r_ * AQ_STRIDE + ch_ * 16,                     \
                     gkl_ + r_ * 256 + ch_ * 16);                                    \
            }                                                                        \
        }                                                                            \
        const char* gvh_ = (const char*)(Vth + bhd * HDIM * SEQLEN + (kb_) * 64);    \
        const char* gvl_ = (const char*)(Vtl + bhd * HDIM * SEQLEN + (kb_) * 64);    \
        {                                                                            \
            int row_ = tid >> 3, ch_ = tid & 7;                                      \
            _Pragma("unroll")                                                        \
            for (int i_ = 0; i_ < 4; i_++) {                                         \
                int r_ = row_ + i_ * 32;                                             \
                cp16(kvb_ + 2 * K_BYTES + r_ * AV_STRIDE + ch_ * 16,                 \
                     gvh_ + (size_t)r_ * SEQLEN * 2 + ch_ * 16);                     \
                cp16(kvb_ + 2 * K_BYTES + VT_BYTES + r_ * AV_STRIDE + ch_ * 16,      \
                     gvl_ + (size_t)r_ * SEQLEN * 2 + ch_ * 16);                     \
            }                                                                        \
        }                                                                            \
        asm volatile("cp.async.commit_group;" ::: "memory");                         \
    } while (0)

    const int nt = 2 * qt + 2;
    LOADKV(0, 0);
    LOADKV(1, 1);

    const uint32_t aQoff = (warp * 16 + (lane & 15)) * AQ_STRIDE + ((lane >> 4) << 4);
    const uint32_t bKoff = ((lane & 7) + ((lane & 16) >> 1)) * AQ_STRIDE + (lane & 8) * 2;
    const uint32_t bVoff = ((lane & 7) + ((lane & 16) >> 1)) * AV_STRIDE + (lane & 8) * 2;

    float o[16][4];
#pragma unroll
    for (int j = 0; j < 16; j++)
#pragma unroll
        for (int c = 0; c < 4; c++) o[j][c] = 0.f;
    float m_run[2] = {-1e30f, -1e30f}, l_run[2] = {0.f, 0.f};

    for (int kb = 0; kb < nt; kb++) {
        const uint32_t kvb = sKV + (kb & 1) * KVBUF_BYTES;
        if (kb + 1 < nt) asm volatile("cp.async.wait_group 1;" ::: "memory");
        else             asm volatile("cp.async.wait_group 0;" ::: "memory");
        __syncthreads();

        float s[8][4];
#pragma unroll
        for (int j = 0; j < 8; j++)
#pragma unroll
            for (int c = 0; c < 4; c++) s[j][c] = 0.f;

#pragma unroll
        for (int ks = 0; ks < 8; ks++) {
            uint32_t ah[4], al[4];
            ldsm4(ah, sQh + aQoff + ks * 32);
            ldsm4(al, sQl + aQoff + ks * 32);
#pragma unroll
            for (int nb = 0; nb < 4; nb++) {
                uint32_t kh4[4], kl4[4];
                ldsm4(kh4, kvb + bKoff + nb * 16 * AQ_STRIDE + ks * 32);
                ldsm4(kl4, kvb + K_BYTES + bKoff + nb * 16 * AQ_STRIDE + ks * 32);
                mma16816(s[nb * 2], ah, kh4);
                mma16816(s[nb * 2], al, kh4);
                mma16816(s[nb * 2], ah, kl4);
                mma16816(s[nb * 2 + 1], ah, kh4 + 2);
                mma16816(s[nb * 2 + 1], al, kh4 + 2);
                mma16816(s[nb * 2 + 1], ah, kl4 + 2);
            }
        }

        if (kb >= 2 * qt) {
            int r0 = qt * 128 + warp * 16 + (lane >> 2);
            int c0 = kb * 64 + (lane & 3) * 2;
#pragma unroll
            for (int j = 0; j < 8; j++)
#pragma unroll
                for (int c = 0; c < 4; c++) {
                    int col = c0 + j * 8 + (c & 1);
                    int row = r0 + ((c & 2) ? 8 : 0);
                    if (col > row) s[j][c] = -1e30f;
                }
        }

        float mloc[2] = {-1e30f, -1e30f};
#pragma unroll
        for (int j = 0; j < 8; j++) {
            mloc[0] = fmaxf(mloc[0], fmaxf(s[j][0], s[j][1]));
            mloc[1] = fmaxf(mloc[1], fmaxf(s[j][2], s[j][3]));
        }
        float mnew[2], alpha[2], rs[2];
#pragma unroll
        for (int h2 = 0; h2 < 2; h2++) {
            mloc[h2] = fmaxf(mloc[h2], __shfl_xor_sync(0xffffffffu, mloc[h2], 1));
            mloc[h2] = fmaxf(mloc[h2], __shfl_xor_sync(0xffffffffu, mloc[h2], 2));
            mnew[h2] = fmaxf(m_run[h2], mloc[h2]);
            alpha[h2] = exp2f(m_run[h2] - mnew[h2]);
            rs[h2] = 0.f;
        }
#pragma unroll
        for (int j = 0; j < 8; j++) {
            s[j][0] = exp2f(s[j][0] - mnew[0]);
            s[j][1] = exp2f(s[j][1] - mnew[0]);
            s[j][2] = exp2f(s[j][2] - mnew[1]);
            s[j][3] = exp2f(s[j][3] - mnew[1]);
            rs[0] += s[j][0] + s[j][1];
            rs[1] += s[j][2] + s[j][3];
        }
#pragma unroll
        for (int h2 = 0; h2 < 2; h2++) {
            rs[h2] += __shfl_xor_sync(0xffffffffu, rs[h2], 1);
            rs[h2] += __shfl_xor_sync(0xffffffffu, rs[h2], 2);
            l_run[h2] = l_run[h2] * alpha[h2] + rs[h2];
            m_run[h2] = mnew[h2];
        }
#pragma unroll
        for (int j = 0; j < 16; j++) {
            o[j][0] *= alpha[0];
            o[j][1] *= alpha[0];
            o[j][2] *= alpha[1];
            o[j][3] *= alpha[1];
        }

#pragma unroll
        for (int kc = 0; kc < 4; kc++) {
            uint32_t pah[4], pal[4];
            split2(s[2 * kc][0], s[2 * kc][1], pah[0], pal[0]);
            split2(s[2 * kc][2], s[2 * kc][3], pah[1], pal[1]);
            split2(s[2 * kc + 1][0], s[2 * kc + 1][1], pah[2], pal[2]);
            split2(s[2 * kc + 1][2], s[2 * kc + 1][3], pah[3], pal[3]);
#pragma unroll
            for (int nb = 0; nb < 8; nb++) {
                uint32_t vh4[4], vl4[4];
                ldsm4(vh4, kvb + 2 * K_BYTES + bVoff + nb * 16 * AV_STRIDE + kc * 32);
                ldsm4(vl4, kvb + 2 * K_BYTES + VT_BYTES + bVoff + nb * 16 * AV_STRIDE + kc * 32);
                mma16816(o[nb * 2], pah, vh4);
                mma16816(o[nb * 2], pal, vh4);
                mma16816(o[nb * 2], pah, vl4);
                mma16816(o[nb * 2 + 1], pah, vh4 + 2);
                mma16816(o[nb * 2 + 1], pal, vh4 + 2);
                mma16816(o[nb * 2 + 1], pah, vl4 + 2);
            }
        }

        if (kb + 2 < nt) {
            __syncthreads();
            LOADKV(kb + 2, kb & 1);
        }
    }

    float inv[2] = {1.f / l_run[0], 1.f / l_run[1]};
    size_t trow = (size_t)b * SEQLEN + qt * 128 + warp * 16 + (lane >> 2);
#pragma unroll
    for (int j = 0; j < 16; j++) {
        int c0 = j * 8 + (lane & 3) * 2;
#pragma unroll
        for (int h2 = 0; h2 < 2; h2++) {
            size_t t = trow + h2 * 8;
            float v0 = o[j][h2 * 2] * inv[h2];
            float v1 = o[j][h2 * 2 + 1] * inv[h2];
            uint32_t hi, lo;
            split2(v0, v1, hi, lo);
            *(uint32_t*)(Oh + t * DIM + h * HDIM + c0) = hi;
            *(uint32_t*)(Ol + t * DIM + h * HDIM + c0) = lo;
        }
    }
}

// ---------------------------------------------------------------------------
extern "C" void kernel_launch(void* const* d_in, const int* in_sizes, int n_in,
                              void* d_out, int out_size) {
    const float* x  = (const float*)d_in[0];
    const float* fc = (const float*)d_in[1];
    const float* wq = (const float*)d_in[4];
    const float* wk = (const float*)d_in[5];
    const float* wv = (const float*)d_in[6];
    const float* wo = (const float*)d_in[7];

    float* out = (float*)d_out;
    float* Kh = out + OUT_ELEMS;
    float* Vh = Kh + OUT_ELEMS;

    float* qbuf;
    __nv_bfloat16 *xh, *xl, *wh, *wl, *ah, *al, *qh, *ql, *kbh, *kbl, *vth, *vtl;
    cudaGetSymbolAddress((void**)&qbuf, g_Q);
    cudaGetSymbolAddress((void**)&xh, g_xh);
    cudaGetSymbolAddress((void**)&xl, g_xl);
    cudaGetSymbolAddress((void**)&wh, g_wh);
    cudaGetSymbolAddress((void**)&wl, g_wl);
    cudaGetSymbolAddress((void**)&ah, g_ah);
    cudaGetSymbolAddress((void**)&al, g_al);
    cudaGetSymbolAddress((void**)&qh, g_qh);
    cudaGetSymbolAddress((void**)&ql, g_ql);
    cudaGetSymbolAddress((void**)&kbh, g_kh);
    cudaGetSymbolAddress((void**)&kbl, g_kl);
    cudaGetSymbolAddress((void**)&vth, g_vth);
    cudaGetSymbolAddress((void**)&vtl, g_vtl);

    const size_t WSZ = (size_t)DIM * DIM;
    const int cblocks = (int)(WSZ / 4 / 256);

    convert_split<<<cblocks, 256>>>(x, xh, xl);
    convert_split<<<cblocks, 256>>>(wq, wh + 0 * WSZ, wl + 0 * WSZ);
    convert_split<<<cblocks, 256>>>(wk, wh + 1 * WSZ, wl + 1 * WSZ);
    convert_split<<<cblocks, 256>>>(wv, wh + 2 * WSZ, wl + 2 * WSZ);
    convert_split<<<cblocks, 256>>>(wo, wh + 3 * WSZ, wl + 3 * WSZ);

    cudaFuncSetAttribute(gemm_mma, cudaFuncAttributeMaxDynamicSharedMemorySize, GEMM_SMEM);

    // Fused QKV projection: B rows 0..12287 of concatenated [wq;wk;wv]
    gemm_mma<<<dim3(96, NTOK / 256), 256, GEMM_SMEM>>>(xh, xl, wh, wl, qbuf, Kh, Vh);

    int rtotal = BSZ * SEQLEN * NHEADS * (HDIM / 2);
    rotary_convert<<<rtotal / 256, 256>>>(qbuf, Kh, fc, qh, ql, kbh, kbl);
    v_transpose<<<dim3(SEQLEN / 32, HDIM / 32, BSZ * NHEADS), dim3(32, 8)>>>(Vh, vth, vtl);

    cudaFuncSetAttribute(flash_attn, cudaFuncAttributeMaxDynamicSharedMemorySize, ATTN_SMEM);
    flash_attn<<<dim3(SEQLEN / 128, NHEADS, BSZ), 256, ATTN_SMEM>>>(
        qh, ql, kbh, kbl, vth, vtl, ah, al);

    // Output projection
    gemm_mma<<<dim3(32, NTOK / 256), 256, GEMM_SMEM>>>(
        ah, al, wh + 3 * WSZ, wl + 3 * WSZ, out, out, out);
}

// round 6
// speedup vs baseline: 4.0833x; 1.3011x over previous
#include <cuda_runtime.h>
#include <cuda_bf16.h>
#include <cstdint>

#define BSZ 2
#define SEQLEN 2048
#define NHEADS 32
#define HDIM 128
#define DIM 4096
#define NTOK (BSZ * SEQLEN)              // 4096
#define OUT_ELEMS ((size_t)NTOK * DIM)   // 16,777,216

// ---------------- GEMM tiling: 256x128 CTA tile, BK=32, pre-tiled GMEM -------
#define BK 32
#define CHUNKS (DIM / BK)                // 128
#define A_TILE_B 16384                   // 256 rows x 64 B
#define B_TILE_B 8192                    // 128 rows x 64 B
#define STAGE_B (2 * A_TILE_B + 2 * B_TILE_B)   // 49152
#define NSTAGE 4
#define GEMM_SMEM (NSTAGE * STAGE_B + 64)       // 196672 B

// ---------------- attention tiling ----------------
#define AQ_STRIDE 272                    // bytes per Q/K smem row (136 bf16)
#define AV_STRIDE 144                    // bytes per Vt smem row (72 bf16)
#define Q_BYTES (128 * AQ_STRIDE)        // 34816
#define K_BYTES (64 * AQ_STRIDE)         // 17408
#define VT_BYTES (128 * AV_STRIDE)       // 18432
#define KVBUF_BYTES (2 * K_BYTES + 2 * VT_BYTES)   // 71680
#define ATTN_SMEM (2 * Q_BYTES + 2 * KVBUF_BYTES)  // 212992

// ---------------- scratch (device globals; no allocation allowed) -----------
__device__ __align__(256) float g_Q[OUT_ELEMS];
__device__ __align__(256) __nv_bfloat16 g_xh[OUT_ELEMS];
__device__ __align__(256) __nv_bfloat16 g_xl[OUT_ELEMS];
__device__ __align__(256) __nv_bfloat16 g_wh[4ull * DIM * DIM];
__device__ __align__(256) __nv_bfloat16 g_wl[4ull * DIM * DIM];
__device__ __align__(256) __nv_bfloat16 g_ah[OUT_ELEMS];
__device__ __align__(256) __nv_bfloat16 g_al[OUT_ELEMS];
__device__ __align__(256) __nv_bfloat16 g_qh[OUT_ELEMS];
__device__ __align__(256) __nv_bfloat16 g_ql[OUT_ELEMS];
__device__ __align__(256) __nv_bfloat16 g_kh[OUT_ELEMS];
__device__ __align__(256) __nv_bfloat16 g_kl[OUT_ELEMS];
__device__ __align__(256) __nv_bfloat16 g_vth[OUT_ELEMS];
__device__ __align__(256) __nv_bfloat16 g_vtl[OUT_ELEMS];

// ---------------- PTX helpers ------------------------------------------------
__device__ __forceinline__ uint32_t smem_u32(const void* p) {
    uint32_t a;
    asm("{ .reg .u64 t; cvta.to.shared.u64 t, %1; cvt.u32.u64 %0, t; }" : "=r"(a) : "l"(p));
    return a;
}
__device__ __forceinline__ void cp16(uint32_t dst, const void* src) {
    asm volatile("cp.async.cg.shared.global [%0], [%1], 16;" :: "r"(dst), "l"(src));
}
__device__ __forceinline__ void bulk_cp(uint32_t dst, const void* src, uint32_t bytes,
                                        uint32_t mbar) {
    asm volatile(
        "cp.async.bulk.shared::cta.global.mbarrier::complete_tx::bytes [%0], [%1], %2, [%3];"
        :: "r"(dst), "l"(src), "r"(bytes), "r"(mbar) : "memory");
}
__device__ __forceinline__ void mbar_expect(uint32_t mbar, uint32_t bytes) {
    asm volatile("mbarrier.arrive.expect_tx.shared.b64 _, [%0], %1;"
                 :: "r"(mbar), "r"(bytes) : "memory");
}
__device__ __forceinline__ void mbar_wait(uint32_t mbar, uint32_t parity) {
    asm volatile(
        "{\n\t.reg .pred P;\n\t"
        "LAB%=:\n\t"
        "mbarrier.try_wait.parity.acquire.cta.shared::cta.b64 P, [%0], %1, 0x989680;\n\t"
        "@!P bra LAB%=;\n\t}"
        :: "r"(mbar), "r"(parity) : "memory");
}
__device__ __forceinline__ void ldsm4(uint32_t* r, uint32_t addr) {
    asm volatile("ldmatrix.sync.aligned.m8n8.x4.shared.b16 {%0,%1,%2,%3}, [%4];"
        : "=r"(r[0]), "=r"(r[1]), "=r"(r[2]), "=r"(r[3]) : "r"(addr));
}
__device__ __forceinline__ void mma16816(float* c, const uint32_t* a, const uint32_t* b) {
    asm volatile("mma.sync.aligned.m16n8k16.row.col.f32.bf16.bf16.f32 "
        "{%0,%1,%2,%3}, {%4,%5,%6,%7}, {%8,%9}, {%0,%1,%2,%3};"
        : "+f"(c[0]), "+f"(c[1]), "+f"(c[2]), "+f"(c[3])
        : "r"(a[0]), "r"(a[1]), "r"(a[2]), "r"(a[3]), "r"(b[0]), "r"(b[1]));
}
__device__ __forceinline__ void split2(float a, float b, uint32_t& hi, uint32_t& lo) {
    __nv_bfloat162 h = __floats2bfloat162_rn(a, b);
    float ra = a - __bfloat162float(h.x);
    float rb = b - __bfloat162float(h.y);
    __nv_bfloat162 l = __floats2bfloat162_rn(ra, rb);
    hi = *(uint32_t*)&h;
    lo = *(uint32_t*)&l;
}

// ---------------------------------------------------------------------------
// fp32 -> split bf16 hi/lo, pre-tiled+swizzled layouts.
// A layout (256-row tiles): off = ((mt*128+ck)*256 + r)*64 + sw(c16,r)*16
// B layout (128-row tiles): off = ((nt*128+ck)*128 + r)*64 + sw(c16,r)*16
// sw(c,r) = c ^ ((r>>1)&3)
// ---------------------------------------------------------------------------
__global__ __launch_bounds__(256) void convert_A(const float* __restrict__ src,
                                                 __nv_bfloat16* __restrict__ hi,
                                                 __nv_bfloat16* __restrict__ lo) {
    int idx = blockIdx.x * 256 + threadIdx.x;     // 2M chunks of 8 elems
    int r = idx >> 9;
    int k = (idx & 511) << 3;
    const float4* s = (const float4*)(src + ((size_t)r << 12) + k);
    float4 v0 = s[0], v1 = s[1];
    float f[8] = {v0.x, v0.y, v0.z, v0.w, v1.x, v1.y, v1.z, v1.w};
    __nv_bfloat16 h8[8], l8[8];
#pragma unroll
    for (int j = 0; j < 8; j++) {
        h8[j] = __float2bfloat16(f[j]);
        l8[j] = __float2bfloat16(f[j] - __bfloat162float(h8[j]));
    }
    int mt = r >> 8, rr = r & 255, ck = k >> 5, c16 = (k & 31) >> 3;
    size_t off = ((((size_t)(mt * 128 + ck)) * 256 + rr) << 6) +
                 ((c16 ^ ((rr >> 1) & 3)) << 4);
    *(uint4*)((char*)hi + off) = *(uint4*)h8;
    *(uint4*)((char*)lo + off) = *(uint4*)l8;
}

__global__ __launch_bounds__(256) void convert_B(const float* __restrict__ src,
                                                 __nv_bfloat16* __restrict__ hi,
                                                 __nv_bfloat16* __restrict__ lo) {
    int idx = blockIdx.x * 256 + threadIdx.x;
    int r = idx >> 9;
    int k = (idx & 511) << 3;
    const float4* s = (const float4*)(src + ((size_t)r << 12) + k);
    float4 v0 = s[0], v1 = s[1];
    float f[8] = {v0.x, v0.y, v0.z, v0.w, v1.x, v1.y, v1.z, v1.w};
    __nv_bfloat16 h8[8], l8[8];
#pragma unroll
    for (int j = 0; j < 8; j++) {
        h8[j] = __float2bfloat16(f[j]);
        l8[j] = __float2bfloat16(f[j] - __bfloat162float(h8[j]));
    }
    int nt = r >> 7, rr = r & 127, ck = k >> 5, c16 = (k & 31) >> 3;
    size_t off = ((((size_t)(nt * 128 + ck)) * 128 + rr) << 6) +
                 ((c16 ^ ((rr >> 1) & 3)) << 4);
    *(uint4*)((char*)hi + off) = *(uint4*)h8;
    *(uint4*)((char*)lo + off) = *(uint4*)l8;
}

// ---------------------------------------------------------------------------
// Split-bf16 mma.sync GEMM, pre-tiled operands, cp.async.bulk pipeline.
// 256x128 CTA tile, BK=32, 4 stages, 8 warps of 64x64.
// ---------------------------------------------------------------------------
__global__ __launch_bounds__(256)
void gemm_mma(const __nv_bfloat16* __restrict__ Ah, const __nv_bfloat16* __restrict__ Al,
              const __nv_bfloat16* __restrict__ Bh, const __nv_bfloat16* __restrict__ Bl,
              float* __restrict__ C0, float* __restrict__ C1, float* __restrict__ C2) {
    extern __shared__ char sm_raw[];
    const uint32_t base = smem_u32(sm_raw);
    const uint32_t mb = base + NSTAGE * STAGE_B;
    const int tid = threadIdx.x;
    const int warp = tid >> 5, lane = tid & 31;
    const int wm = warp & 3, wn = warp >> 2;     // 4 x 2 warp grid, warp 64x64
    const int nt = blockIdx.x, mt = blockIdx.y;

    const char* srcAh = (const char*)Ah;
    const char* srcAl = (const char*)Al;
    const char* srcBh = (const char*)Bh;
    const char* srcBl = (const char*)Bl;
    const size_t mtC = (size_t)mt * CHUNKS;
    const size_t ntC = (size_t)nt * CHUNKS;

    if (tid == 0) {
#pragma unroll
        for (int s = 0; s < NSTAGE; s++)
            asm volatile("mbarrier.init.shared.b64 [%0], %1;" :: "r"(mb + 8 * s), "r"(1u) : "memory");
        asm volatile("fence.proxy.async.shared::cta;" ::: "memory");
    }
    __syncthreads();

#define ISSUE(c, s)                                                              \
    do {                                                                         \
        if (tid == 0) {                                                          \
            uint32_t mb_ = mb + 8 * (s);                                         \
            mbar_expect(mb_, STAGE_B);                                           \
            uint32_t st_ = base + (s) * STAGE_B;                                 \
            bulk_cp(st_, srcAh + (mtC + (c)) * A_TILE_B, A_TILE_B, mb_);         \
            bulk_cp(st_ + A_TILE_B, srcAl + (mtC + (c)) * A_TILE_B, A_TILE_B, mb_); \
            bulk_cp(st_ + 2 * A_TILE_B, srcBh + (ntC + (c)) * B_TILE_B, B_TILE_B, mb_); \
            bulk_cp(st_ + 2 * A_TILE_B + B_TILE_B, srcBl + (ntC + (c)) * B_TILE_B, B_TILE_B, mb_); \
        }                                                                        \
    } while (0)

    ISSUE(0, 0);
    ISSUE(1, 1);
    ISSUE(2, 2);

    // per-thread ldsm address components (swizzled 64B rows)
    const int rowA = wm * 64 + (lane & 15);
    const int xa = (rowA >> 1) & 3;
    const int lsA = lane >> 4;
    const uint32_t cA0 = (uint32_t)((lsA ^ xa) << 4);
    const uint32_t cA1 = (uint32_t)(((2 | lsA) ^ xa) << 4);
    const uint32_t aRow = (uint32_t)rowA * 64;

    const int rowB = wn * 64 + (lane & 7) + ((lane & 16) >> 1);
    const int xb = (rowB >> 1) & 3;
    const int lsB = (lane & 8) >> 3;
    const uint32_t cB0 = (uint32_t)((lsB ^ xb) << 4);
    const uint32_t cB1 = (uint32_t)(((2 | lsB) ^ xb) << 4);
    const uint32_t bRow = (uint32_t)rowB * 64;

    float c[4][8][4];
#pragma unroll
    for (int mi = 0; mi < 4; mi++)
#pragma unroll
        for (int ni = 0; ni < 8; ni++)
#pragma unroll
            for (int j = 0; j < 4; j++) c[mi][ni][j] = 0.f;

    for (int ck = 0; ck < CHUNKS; ck++) {
        const int s = ck & 3;
        mbar_wait(mb + 8 * s, (ck >> 2) & 1);

        const uint32_t sb = base + s * STAGE_B;
        const uint32_t aHi = sb + aRow;
        const uint32_t aLo = aHi + A_TILE_B;
        const uint32_t bHi = sb + 2 * A_TILE_B + bRow;
        const uint32_t bLo = bHi + B_TILE_B;

#pragma unroll
        for (int kk = 0; kk < 2; kk++) {
            const uint32_t ca = kk ? cA1 : cA0;
            const uint32_t cb = kk ? cB1 : cB0;
            uint32_t bh[16], bl[16];
#pragma unroll
            for (int g = 0; g < 4; g++) {
                ldsm4(bh + g * 4, bHi + g * 1024 + cb);
                ldsm4(bl + g * 4, bLo + g * 1024 + cb);
            }
#pragma unroll
            for (int mi = 0; mi < 4; mi++) {
                uint32_t ah[4], al[4];
                ldsm4(ah, aHi + mi * 1024 + ca);
                ldsm4(al, aLo + mi * 1024 + ca);
#pragma unroll
                for (int ni = 0; ni < 8; ni++) {
                    mma16816(c[mi][ni], ah, &bh[ni * 2]);
                    mma16816(c[mi][ni], al, &bh[ni * 2]);
                    mma16816(c[mi][ni], ah, &bl[ni * 2]);
                }
            }
        }
        __syncthreads();
        if (ck + 3 < CHUNKS) ISSUE(ck + 3, (ck + 3) & 3);
    }

    // epilogue: route by nt>>5 (fused QKV), col block = (nt & 31) * 128
    float* Cb = (nt < 32) ? C0 : (nt < 64) ? C1 : C2;
    float* Cw = Cb + (size_t)(mt * 256 + wm * 64) * DIM + (nt & 31) * 128 + wn * 64;
    const int cr = lane >> 2, cc = (lane & 3) * 2;
#pragma unroll
    for (int mi = 0; mi < 4; mi++)
#pragma unroll
        for (int ni = 0; ni < 8; ni++) {
            float* p0 = Cw + (size_t)(mi * 16 + cr) * DIM + ni * 8 + cc;
            float* p1 = p0 + 8 * DIM;
            *(float2*)p0 = make_float2(c[mi][ni][0], c[mi][ni][1]);
            *(float2*)p1 = make_float2(c[mi][ni][2], c[mi][ni][3]);
        }
}

// ---------------------------------------------------------------------------
// Rotary + bf16 split for Q (scaled by log2e/sqrt(d)) and K.
// ---------------------------------------------------------------------------
__global__ __launch_bounds__(256) void rotary_convert(
        const float* __restrict__ Q, float* __restrict__ Kf,
        const float* __restrict__ fc,
        __nv_bfloat16* __restrict__ qh, __nv_bfloat16* __restrict__ ql,
        __nv_bfloat16* __restrict__ kh, __nv_bfloat16* __restrict__ kl) {
    const float QSC = 1.44269504088896f / 11.3137084989848f;  // log2e / sqrt(128)
    int idx = blockIdx.x * blockDim.x + threadIdx.x;
    int p = idx & 63;
    int h = (idx >> 6) & 31;
    int s = (idx >> 11) & (SEQLEN - 1);
    int b = idx >> 22;

    float c = fc[(s * 64 + p) * 2];
    float sn = fc[(s * 64 + p) * 2 + 1];

    size_t in = (((size_t)(b * SEQLEN + s) * NHEADS) + h) * HDIM + p * 2;
    size_t out = (((size_t)(b * NHEADS + h) * SEQLEN) + s) * HDIM + p * 2;

    float2 q = *(float2*)(Q + in);
    float2 k = *(float2*)(Kf + in);
    float2 qo = {q.x * c - q.y * sn, q.x * sn + q.y * c};
    float2 ko = {k.x * c - k.y * sn, k.x * sn + k.y * c};
    *(float2*)(Kf + in) = ko;

    uint32_t hi, lo;
    split2(qo.x * QSC, qo.y * QSC, hi, lo);
    *(uint32_t*)(qh + out) = hi;
    *(uint32_t*)(ql + out) = lo;
    split2(ko.x, ko.y, hi, lo);
    *(uint32_t*)(kh + out) = hi;
    *(uint32_t*)(kl + out) = lo;
}

// ---------------------------------------------------------------------------
// V transpose + split: fp32 [B,S,H,D] -> bf16 hi/lo [B,H,D,S]
// ---------------------------------------------------------------------------
__global__ __launch_bounds__(256) void v_transpose(const float* __restrict__ V,
                                                   __nv_bfloat16* __restrict__ vth,
                                                   __nv_bfloat16* __restrict__ vtl) {
    __shared__ float t[32][33];
    int s0 = blockIdx.x * 32, d0 = blockIdx.y * 32;
    int bh = blockIdx.z;
    int b = bh >> 5, h = bh & 31;
#pragma unroll
    for (int i = 0; i < 4; i++) {
        int s = s0 + threadIdx.y + i * 8;
        t[threadIdx.y + i * 8][threadIdx.x] =
            V[(((size_t)(b * SEQLEN + s) * NHEADS) + h) * HDIM + d0 + threadIdx.x];
    }
    __syncthreads();
#pragma unroll
    for (int i = 0; i < 4; i++) {
        int d = d0 + threadIdx.y + i * 8;
        float v = t[threadIdx.x][threadIdx.y + i * 8];
        __nv_bfloat16 hb = __float2bfloat16(v);
        size_t o = ((size_t)bh * HDIM + d) * SEQLEN + s0 + threadIdx.x;
        vth[o] = hb;
        vtl[o] = __float2bfloat16(v - __bfloat162float(hb));
    }
}

// ---------------------------------------------------------------------------
// Flash attention, split-bf16 mma.sync. Epilogue writes tiled-A layout
// (consumed directly by the Wo GEMM). Otherwise as round 4/5.
// ---------------------------------------------------------------------------
__global__ __launch_bounds__(256)
void flash_attn(const __nv_bfloat16* __restrict__ Qh, const __nv_bfloat16* __restrict__ Ql,
                const __nv_bfloat16* __restrict__ Kbh, const __nv_bfloat16* __restrict__ Kbl,
                const __nv_bfloat16* __restrict__ Vth, const __nv_bfloat16* __restrict__ Vtl,
                __nv_bfloat16* __restrict__ Oh, __nv_bfloat16* __restrict__ Ol) {
    extern __shared__ char sm_raw[];
    const uint32_t base = smem_u32(sm_raw);
    const int tid = threadIdx.x, warp = tid >> 5, lane = tid & 31;
    const int qt = blockIdx.x, h = blockIdx.y, b = blockIdx.z;
    const size_t bhd = (size_t)(b * NHEADS + h);

    const uint32_t sQh = base, sQl = base + Q_BYTES;
    const uint32_t sKV = base + 2 * Q_BYTES;

    {
        const char* gq = (const char*)(Qh + (bhd * SEQLEN + qt * 128) * HDIM);
        const char* gl = (const char*)(Ql + (bhd * SEQLEN + qt * 128) * HDIM);
        int row = tid >> 4, ch = tid & 15;
#pragma unroll
        for (int i = 0; i < 8; i++) {
            int r = row + i * 16;
            cp16(sQh + r * AQ_STRIDE + ch * 16, gq + r * 256 + ch * 16);
            cp16(sQl + r * AQ_STRIDE + ch * 16, gl + r * 256 + ch * 16);
        }
    }

#define LOADKV(kb_, p_)                                                              \
    do {                                                                             \
        uint32_t kvb_ = sKV + (p_) * KVBUF_BYTES;                                    \
        const char* gkh_ = (const char*)(Kbh + (bhd * SEQLEN + (kb_) * 64) * HDIM);  \
        const char* gkl_ = (const char*)(Kbl + (bhd * SEQLEN + (kb_) * 64) * HDIM);  \
        {                                                                            \
            int row_ = tid >> 4, ch_ = tid & 15;                                     \
            _Pragma("unroll")                                                        \
            for (int i_ = 0; i_ < 4; i_++) {                                         \
                int r_ = row_ + i_ * 16;                                             \
                cp16(kvb_ + r_ * AQ_STRIDE + ch_ * 16, gkh_ + r_ * 256 + ch_ * 16);  \
                cp16(kvb_ + K_BYTES + r_ * AQ_STRIDE + ch_ * 16,                     \
                     gkl_ + r_ * 256 + ch_ * 16);                                    \
            }                                                                        \
        }                                                                            \
        const char* gvh_ = (const char*)(Vth + bhd * HDIM * SEQLEN + (kb_) * 64);    \
        const char* gvl_ = (const char*)(Vtl + bhd * HDIM * SEQLEN + (kb_) * 64);    \
        {                                                                            \
            int row_ = tid >> 3, ch_ = tid & 7;                                      \
            _Pragma("unroll")                                                        \
            for (int i_ = 0; i_ < 4; i_++) {                                         \
                int r_ = row_ + i_ * 32;                                             \
                cp16(kvb_ + 2 * K_BYTES + r_ * AV_STRIDE + ch_ * 16,                 \
                     gvh_ + (size_t)r_ * SEQLEN * 2 + ch_ * 16);                     \
                cp16(kvb_ + 2 * K_BYTES + VT_BYTES + r_ * AV_STRIDE + ch_ * 16,      \
                     gvl_ + (size_t)r_ * SEQLEN * 2 + ch_ * 16);                     \
            }                                                                        \
        }                                                                            \
        asm volatile("cp.async.commit_group;" ::: "memory");                         \
    } while (0)

    const int nt = 2 * qt + 2;
    LOADKV(0, 0);
    LOADKV(1, 1);

    const uint32_t aQoff = (warp * 16 + (lane & 15)) * AQ_STRIDE + ((lane >> 4) << 4);
    const uint32_t bKoff = ((lane & 7) + ((lane & 16) >> 1)) * AQ_STRIDE + (lane & 8) * 2;
    const uint32_t bVoff = ((lane & 7) + ((lane & 16) >> 1)) * AV_STRIDE + (lane & 8) * 2;

    float o[16][4];
#pragma unroll
    for (int j = 0; j < 16; j++)
#pragma unroll
        for (int c = 0; c < 4; c++) o[j][c] = 0.f;
    float m_run[2] = {-1e30f, -1e30f}, l_run[2] = {0.f, 0.f};

    for (int kb = 0; kb < nt; kb++) {
        const uint32_t kvb = sKV + (kb & 1) * KVBUF_BYTES;
        if (kb + 1 < nt) asm volatile("cp.async.wait_group 1;" ::: "memory");
        else             asm volatile("cp.async.wait_group 0;" ::: "memory");
        __syncthreads();

        float s[8][4];
#pragma unroll
        for (int j = 0; j < 8; j++)
#pragma unroll
            for (int c = 0; c < 4; c++) s[j][c] = 0.f;

#pragma unroll
        for (int ks = 0; ks < 8; ks++) {
            uint32_t ah[4], al[4];
            ldsm4(ah, sQh + aQoff + ks * 32);
            ldsm4(al, sQl + aQoff + ks * 32);
#pragma unroll
            for (int nb = 0; nb < 4; nb++) {
                uint32_t kh4[4], kl4[4];
                ldsm4(kh4, kvb + bKoff + nb * 16 * AQ_STRIDE + ks * 32);
                ldsm4(kl4, kvb + K_BYTES + bKoff + nb * 16 * AQ_STRIDE + ks * 32);
                mma16816(s[nb * 2], ah, kh4);
                mma16816(s[nb * 2], al, kh4);
                mma16816(s[nb * 2], ah, kl4);
                mma16816(s[nb * 2 + 1], ah, kh4 + 2);
                mma16816(s[nb * 2 + 1], al, kh4 + 2);
                mma16816(s[nb * 2 + 1], ah, kl4 + 2);
            }
        }

        if (kb >= 2 * qt) {
            int r0 = qt * 128 + warp * 16 + (lane >> 2);
            int c0 = kb * 64 + (lane & 3) * 2;
#pragma unroll
            for (int j = 0; j < 8; j++)
#pragma unroll
                for (int c = 0; c < 4; c++) {
                    int col = c0 + j * 8 + (c & 1);
                    int row = r0 + ((c & 2) ? 8 : 0);
                    if (col > row) s[j][c] = -1e30f;
                }
        }

        float mloc[2] = {-1e30f, -1e30f};
#pragma unroll
        for (int j = 0; j < 8; j++) {
            mloc[0] = fmaxf(mloc[0], fmaxf(s[j][0], s[j][1]));
            mloc[1] = fmaxf(mloc[1], fmaxf(s[j][2], s[j][3]));
        }
        float mnew[2], alpha[2], rs[2];
#pragma unroll
        for (int h2 = 0; h2 < 2; h2++) {
            mloc[h2] = fmaxf(mloc[h2], __shfl_xor_sync(0xffffffffu, mloc[h2], 1));
            mloc[h2] = fmaxf(mloc[h2], __shfl_xor_sync(0xffffffffu, mloc[h2], 2));
            mnew[h2] = fmaxf(m_run[h2], mloc[h2]);
            alpha[h2] = exp2f(m_run[h2] - mnew[h2]);
            rs[h2] = 0.f;
        }
#pragma unroll
        for (int j = 0; j < 8; j++) {
            s[j][0] = exp2f(s[j][0] - mnew[0]);
            s[j][1] = exp2f(s[j][1] - mnew[0]);
            s[j][2] = exp2f(s[j][2] - mnew[1]);
            s[j][3] = exp2f(s[j][3] - mnew[1]);
            rs[0] += s[j][0] + s[j][1];
            rs[1] += s[j][2] + s[j][3];
        }
#pragma unroll
        for (int h2 = 0; h2 < 2; h2++) {
            rs[h2] += __shfl_xor_sync(0xffffffffu, rs[h2], 1);
            rs[h2] += __shfl_xor_sync(0xffffffffu, rs[h2], 2);
            l_run[h2] = l_run[h2] * alpha[h2] + rs[h2];
            m_run[h2] = mnew[h2];
        }
#pragma unroll
        for (int j = 0; j < 16; j++) {
            o[j][0] *= alpha[0];
            o[j][1] *= alpha[0];
            o[j][2] *= alpha[1];
            o[j][3] *= alpha[1];
        }

#pragma unroll
        for (int kc = 0; kc < 4; kc++) {
            uint32_t pah[4], pal[4];
            split2(s[2 * kc][0], s[2 * kc][1], pah[0], pal[0]);
            split2(s[2 * kc][2], s[2 * kc][3], pah[1], pal[1]);
            split2(s[2 * kc + 1][0], s[2 * kc + 1][1], pah[2], pal[2]);
            split2(s[2 * kc + 1][2], s[2 * kc + 1][3], pah[3], pal[3]);
#pragma unroll
            for (int nb = 0; nb < 8; nb++) {
                uint32_t vh4[4], vl4[4];
                ldsm4(vh4, kvb + 2 * K_BYTES + bVoff + nb * 16 * AV_STRIDE + kc * 32);
                ldsm4(vl4, kvb + 2 * K_BYTES + VT_BYTES + bVoff + nb * 16 * AV_STRIDE + kc * 32);
                mma16816(o[nb * 2], pah, vh4);
                mma16816(o[nb * 2], pal, vh4);
                mma16816(o[nb * 2], pah, vl4);
                mma16816(o[nb * 2 + 1], pah, vh4 + 2);
                mma16816(o[nb * 2 + 1], pal, vh4 + 2);
                mma16816(o[nb * 2 + 1], pah, vl4 + 2);
            }
        }

        if (kb + 2 < nt) {
            __syncthreads();
            LOADKV(kb + 2, kb & 1);
        }
    }

    // normalize + write bf16 hi/lo in tiled-A layout for the Wo GEMM
    float inv[2] = {1.f / l_run[0], 1.f / l_run[1]};
    int trow = b * SEQLEN + qt * 128 + warp * 16 + (lane >> 2);
#pragma unroll
    for (int j = 0; j < 16; j++) {
        int c0 = j * 8 + (lane & 3) * 2;
        int k = h * HDIM + c0;
        int ck = k >> 5, c16 = (k & 31) >> 3, bo = (k & 7) * 2;
#pragma unroll
        for (int h2 = 0; h2 < 2; h2++) {
            int t = trow + h2 * 8;
            int mtA = t >> 8, rr = t & 255;
            size_t off = ((((size_t)(mtA * 128 + ck)) * 256 + rr) << 6) +
                         ((c16 ^ ((rr >> 1) & 3)) << 4) + bo;
            float v0 = o[j][h2 * 2] * inv[h2];
            float v1 = o[j][h2 * 2 + 1] * inv[h2];
            uint32_t hi, lo;
            split2(v0, v1, hi, lo);
            *(uint32_t*)((char*)Oh + off) = hi;
            *(uint32_t*)((char*)Ol + off) = lo;
        }
    }
}

// ---------------------------------------------------------------------------
extern "C" void kernel_launch(void* const* d_in, const int* in_sizes, int n_in,
                              void* d_out, int out_size) {
    const float* x  = (const float*)d_in[0];
    const float* fc = (const float*)d_in[1];
    const float* wq = (const float*)d_in[4];
    const float* wk = (const float*)d_in[5];
    const float* wv = (const float*)d_in[6];
    const float* wo = (const float*)d_in[7];

    float* out = (float*)d_out;
    float* Kh = out + OUT_ELEMS;
    float* Vh = Kh + OUT_ELEMS;

    float* qbuf;
    __nv_bfloat16 *xh, *xl, *wh, *wl, *ah, *al, *qh, *ql, *kbh, *kbl, *vth, *vtl;
    cudaGetSymbolAddress((void**)&qbuf, g_Q);
    cudaGetSymbolAddress((void**)&xh, g_xh);
    cudaGetSymbolAddress((void**)&xl, g_xl);
    cudaGetSymbolAddress((void**)&wh, g_wh);
    cudaGetSymbolAddress((void**)&wl, g_wl);
    cudaGetSymbolAddress((void**)&ah, g_ah);
    cudaGetSymbolAddress((void**)&al, g_al);
    cudaGetSymbolAddress((void**)&qh, g_qh);
    cudaGetSymbolAddress((void**)&ql, g_ql);
    cudaGetSymbolAddress((void**)&kbh, g_kh);
    cudaGetSymbolAddress((void**)&kbl, g_kl);
    cudaGetSymbolAddress((void**)&vth, g_vth);
    cudaGetSymbolAddress((void**)&vtl, g_vtl);

    const size_t WSZ = (size_t)DIM * DIM;
    const int cblocks = (int)(WSZ / 8 / 256);   // 8 elems per thread

    convert_A<<<cblocks, 256>>>(x, xh, xl);
    convert_B<<<cblocks, 256>>>(wq, wh + 0 * WSZ, wl + 0 * WSZ);
    convert_B<<<cblocks, 256>>>(wk, wh + 1 * WSZ, wl + 1 * WSZ);
    convert_B<<<cblocks, 256>>>(wv, wh + 2 * WSZ, wl + 2 * WSZ);
    convert_B<<<cblocks, 256>>>(wo, wh + 3 * WSZ, wl + 3 * WSZ);

    cudaFuncSetAttribute(gemm_mma, cudaFuncAttributeMaxDynamicSharedMemorySize, GEMM_SMEM);

    // Fused QKV projection (B tiles 0..95 span wq, wk, wv)
    gemm_mma<<<dim3(96, NTOK / 256), 256, GEMM_SMEM>>>(xh, xl, wh, wl, qbuf, Kh, Vh);

    int rtotal = BSZ * SEQLEN * NHEADS * (HDIM / 2);
    rotary_convert<<<rtotal / 256, 256>>>(qbuf, Kh, fc, qh, ql, kbh, kbl);
    v_transpose<<<dim3(SEQLEN / 32, HDIM / 32, BSZ * NHEADS), dim3(32, 8)>>>(Vh, vth, vtl);

    cudaFuncSetAttribute(flash_attn, cudaFuncAttributeMaxDynamicSharedMemorySize, ATTN_SMEM);
    flash_attn<<<dim3(SEQLEN / 128, NHEADS, BSZ), 256, ATTN_SMEM>>>(
        qh, ql, kbh, kbl, vth, vtl, ah, al);

    // Output projection (A = attention output in tiled layout)
    gemm_mma<<<dim3(32, NTOK / 256), 256, GEMM_SMEM>>>(
        ah, al, wh + 3 * WSZ, wl + 3 * WSZ, out, out, out);
}